// round 6
// baseline (speedup 1.0000x reference)
#include <cuda_runtime.h>
#include <math.h>
#include <cstdint>

#define T_N  4096
#define EMB  384
#define HID  256
#define NH   4
#define HD   64
#define MD   32
#define S0   33
#define NS   4063

#if defined(__CUDA_ARCH_FEAT_SM103_ALL) || defined(__CUDA_ARCH_FEAT_SM100_ALL) || defined(__CUDA_ARCH_FEAT_SM101_ALL)
#define HAS_TC 1
#else
#define HAS_TC 0
#endif

__device__ float g_h  [T_N * HID];
__device__ float g_x  [T_N * HID];
__device__ float g_Wh [T_N * HID];
__device__ float g_src[NH * T_N];
__device__ float g_dst[NH * T_N];
__device__ float g_dmax[NH];
__device__ float g_scal[4];
__device__ float g_scores[NS];
__device__ float g_cosf[NS];
__device__ float g_aw[NS];

__device__ __forceinline__ float warpSum(float v) {
    #pragma unroll
    for (int o = 16; o; o >>= 1) v += __shfl_xor_sync(0xffffffffu, v, o);
    return v;
}
__device__ __forceinline__ float warpMax(float v) {
    #pragma unroll
    for (int o = 16; o; o >>= 1) v = fmaxf(v, __shfl_xor_sync(0xffffffffu, v, o));
    return v;
}
__device__ float blockSum256(float v) {
    __shared__ float sh[8];
    int w = threadIdx.x >> 5, l = threadIdx.x & 31;
    v = warpSum(v);
    if (l == 0) sh[w] = v;
    __syncthreads();
    float s = (threadIdx.x < 8) ? sh[threadIdx.x] : 0.f;
    if (w == 0) { s = warpSum(s); if (l == 0) sh[0] = s; }
    __syncthreads();
    float r = sh[0];
    __syncthreads();
    return r;
}

__device__ __forceinline__ uint32_t s2u(const void* p) {
    uint32_t a;
    asm("{ .reg .u64 t; cvta.to.shared.u64 t, %1; cvt.u32.u64 %0, t; }"
        : "=r"(a) : "l"(p));
    return a;
}
__device__ __forceinline__ uint32_t sw128(uint32_t off) {
    return off ^ ((off >> 3) & 0x70);
}
__device__ __forceinline__ float ex2f(float x) {
    float r;
    asm("ex2.approx.f32 %0, %1;" : "=f"(r) : "f"(x));
    return r;
}

#if HAS_TC
__device__ __forceinline__ uint32_t elect_one() {
    uint32_t pred;
    asm volatile("{\n\t.reg .pred p;\n\telect.sync _|p, 0xFFFFFFFF;\n\t"
                 "selp.b32 %0, 1, 0, p;\n\t}" : "=r"(pred));
    return pred;
}
__device__ __forceinline__ void mbar_init(uint32_t addr, uint32_t cnt) {
    asm volatile("mbarrier.init.shared.b64 [%0], %1;" :: "r"(addr), "r"(cnt) : "memory");
}
__device__ __forceinline__ void mbar_wait(uint32_t addr, uint32_t parity) {
    asm volatile(
        "{\n\t.reg .pred P;\n\t"
        "WL%=:\n\t"
        "mbarrier.try_wait.parity.acquire.cta.shared::cta.b64 P, [%0], %1, 0x989680;\n\t"
        "@P bra WD%=;\n\t"
        "bra WL%=;\n\t"
        "WD%=:\n\t}"
        :: "r"(addr), "r"(parity) : "memory");
}
__device__ __forceinline__ void mma_tf32_ss(uint32_t d_tmem, uint64_t a_desc,
                                            uint64_t b_desc, uint32_t idesc,
                                            uint32_t en) {
    asm volatile(
        "{\n\t.reg .pred p;\n\tsetp.ne.u32 p, %4, 0;\n\t"
        "tcgen05.mma.cta_group::1.kind::tf32 [%0], %1, %2, %3, {%5, %5, %5, %5}, p;\n\t}"
        :: "r"(d_tmem), "l"(a_desc), "l"(b_desc), "r"(idesc), "r"(en), "r"(0u)
        : "memory");
}
__device__ __forceinline__ void tc_commit(uint32_t mbar) {
    asm volatile(
        "tcgen05.commit.cta_group::1.mbarrier::arrive::one.shared::cluster.b64 [%0];"
        :: "r"(mbar) : "memory");
}
#define TC_LD_X32(r, tmem_addr) \
    asm volatile( \
        "tcgen05.ld.sync.aligned.32x32b.x32.b32 " \
        "{%0, %1, %2, %3, %4, %5, %6, %7, " \
        " %8, %9, %10, %11, %12, %13, %14, %15, " \
        " %16, %17, %18, %19, %20, %21, %22, %23, " \
        " %24, %25, %26, %27, %28, %29, %30, %31}, [%32];" \
        : "=r"((r)[0]),  "=r"((r)[1]),  "=r"((r)[2]),  "=r"((r)[3]), \
          "=r"((r)[4]),  "=r"((r)[5]),  "=r"((r)[6]),  "=r"((r)[7]), \
          "=r"((r)[8]),  "=r"((r)[9]),  "=r"((r)[10]), "=r"((r)[11]), \
          "=r"((r)[12]), "=r"((r)[13]), "=r"((r)[14]), "=r"((r)[15]), \
          "=r"((r)[16]), "=r"((r)[17]), "=r"((r)[18]), "=r"((r)[19]), \
          "=r"((r)[20]), "=r"((r)[21]), "=r"((r)[22]), "=r"((r)[23]), \
          "=r"((r)[24]), "=r"((r)[25]), "=r"((r)[26]), "=r"((r)[27]), \
          "=r"((r)[28]), "=r"((r)[29]), "=r"((r)[30]), "=r"((r)[31]) \
        : "r"(tmem_addr))
#endif // HAS_TC

// smem desc: SW128, version=1, SBO=64, LBO=1
#define DESC_BASE ((2ull << 61) | (1ull << 46) | (64ull << 32) | (1ull << 16))
// idesc: dtype=F32, atype=TF32, btype=TF32, N=64, M=128
#define TF32_IDESC ((1u << 4) | (2u << 7) | (2u << 10) | (8u << 17) | (8u << 24))

// smem offsets: P buf = 2 chunks x 128 rows x 128B = 32KB; B buf = 2 x 64 x 128B = 16KB
#define SM_P0    0
#define SM_B0    32768
#define SM_P1    49152
#define SM_B1    81920
#define SM_TPTR  98304
#define SM_MB0   98320
#define SM_MB1   98328
#define SM_ZF    98336
#define SM_TOTAL (98848 + 1024)

// ======================= generic 16-row GEMM (FFMA2) =======================
#define GEMM_STEP2(WV, KK)                                                    \
    {                                                                         \
        unsigned long long w2;                                                \
        asm("mov.b64 %0, {%1,%1};" : "=l"(w2) : "r"(__float_as_uint(WV)));    \
        const ulonglong2* av = (const ulonglong2*)&sa[(KK) * 16];             \
        ulonglong2 a0 = av[0], a1 = av[1];                                    \
        asm("fma.rn.f32x2 %0, %1, %2, %0;" : "+l"(acc2[0]) : "l"(a0.x), "l"(w2)); \
        asm("fma.rn.f32x2 %0, %1, %2, %0;" : "+l"(acc2[1]) : "l"(a0.y), "l"(w2)); \
        asm("fma.rn.f32x2 %0, %1, %2, %0;" : "+l"(acc2[2]) : "l"(a1.x), "l"(w2)); \
        asm("fma.rn.f32x2 %0, %1, %2, %0;" : "+l"(acc2[3]) : "l"(a1.y), "l"(w2)); \
        ulonglong2 a2 = av[2], a3 = av[3];                                    \
        asm("fma.rn.f32x2 %0, %1, %2, %0;" : "+l"(acc2[4]) : "l"(a2.x), "l"(w2)); \
        asm("fma.rn.f32x2 %0, %1, %2, %0;" : "+l"(acc2[5]) : "l"(a2.y), "l"(w2)); \
        asm("fma.rn.f32x2 %0, %1, %2, %0;" : "+l"(acc2[6]) : "l"(a3.x), "l"(w2)); \
        asm("fma.rn.f32x2 %0, %1, %2, %0;" : "+l"(acc2[7]) : "l"(a3.y), "l"(w2)); \
    }

__global__ void __launch_bounds__(256) gemm16(const float* __restrict__ A,
                                              const float* __restrict__ Wt,
                                              const float* __restrict__ bias,
                                              float* __restrict__ Cout,
                                              int K, int doRelu)
{
    __shared__ __align__(16) float sa[EMB * 16];
    int r0 = blockIdx.x * 16;
    for (int idx = threadIdx.x; idx < 16 * K; idx += 256) {
        int r = idx / K, k = idx - r * K;
        sa[k * 16 + r] = A[(size_t)(r0 + r) * K + k];
    }
    __syncthreads();
    unsigned long long acc2[8];
    #pragma unroll
    for (int p = 0; p < 8; p++) acc2[p] = 0ull;
    int c = threadIdx.x;
    const float4* w4 = (const float4*)(Wt + (size_t)c * K);
    int K4 = K >> 2;
    for (int k4 = 0; k4 < K4; k4++) {
        float4 w = w4[k4];
        int kb = k4 * 4;
        GEMM_STEP2(w.x, kb + 0)
        GEMM_STEP2(w.y, kb + 1)
        GEMM_STEP2(w.z, kb + 2)
        GEMM_STEP2(w.w, kb + 3)
    }
    float b = bias ? bias[c] : 0.f;
    #pragma unroll
    for (int p = 0; p < 8; p++) {
        float lo = __uint_as_float((unsigned)(acc2[p] & 0xffffffffull)) + b;
        float hi = __uint_as_float((unsigned)(acc2[p] >> 32)) + b;
        if (doRelu) { lo = fmaxf(lo, 0.f); hi = fmaxf(hi, 0.f); }
        Cout[(size_t)(r0 + 2 * p)     * HID + c] = lo;
        Cout[(size_t)(r0 + 2 * p + 1) * HID + c] = hi;
    }
}

__global__ void __launch_bounds__(256) rownorm0(int slot)
{
    float v = g_h[threadIdx.x];
    float s = blockSum256(v * v);
    if (threadIdx.x == 0) g_scal[slot] = 1.f / (sqrtf(s) + 1e-8f);
}

__global__ void __launch_bounds__(256) cos_update()
{
    __shared__ float q[HID];
    int tid = threadIdx.x;
    q[tid] = g_h[tid];
    __syncthreads();
    int w = tid >> 5, l = tid & 31;
    int j = blockIdx.x * 8 + w;
    if (j >= NS) return;
    float* s = &g_h[(size_t)(S0 + j) * HID];
    float sv[8];
    float qs = 0.f, ss = 0.f;
    #pragma unroll
    for (int e = 0; e < 8; e++) {
        float x = s[l + 32 * e];
        sv[e] = x;
        qs += q[l + 32 * e] * x;
        ss += x * x;
    }
    qs = warpSum(qs);
    ss = warpSum(ss);
    float cs = qs * g_scal[0] / (sqrtf(ss) + 1e-8f);
    #pragma unroll
    for (int e = 0; e < 8; e++)
        s[l + 32 * e] = sv[e] + 0.8f * q[l + 32 * e] * cs;
}

// warp-per-row layernorm: grid = T_N/8, 8 warps per CTA
__global__ void __launch_bounds__(256) ln2_k(const float* __restrict__ scale,
                                             const float* __restrict__ bias)
{
    __shared__ float sc[HID], bi[HID];
    int tid = threadIdx.x, w = tid >> 5, l = tid & 31;
    sc[tid] = scale[tid];
    bi[tid] = bias[tid];
    __syncthreads();
    int row = blockIdx.x * 8 + w;
    const float* hp = &g_h[(size_t)row * HID];
    float v[8];
    float s = 0.f;
    #pragma unroll
    for (int e = 0; e < 8; e++) { v[e] = hp[l + 32 * e]; s += v[e]; }
    float mu = warpSum(s) * (1.f / HID);
    float ss = 0.f;
    #pragma unroll
    for (int e = 0; e < 8; e++) { v[e] -= mu; ss += v[e] * v[e]; }
    float rs = rsqrtf(warpSum(ss) * (1.f / HID) + 1e-5f);
    float* xp = &g_x[(size_t)row * HID];
    #pragma unroll
    for (int e = 0; e < 8; e++)
        xp[l + 32 * e] = v[e] * rs * sc[l + 32 * e] + bi[l + 32 * e];
}

__global__ void __launch_bounds__(256) srcdst_k(const float* __restrict__ ga)
{
    int w = threadIdx.x >> 5, l = threadIdx.x & 31;
    int gid = blockIdx.x * 8 + w;
    int n = gid >> 2, hh = gid & 3;
    const float* wp = &g_Wh[(size_t)n * HID + hh * HD];
    float v0 = wp[l], v1 = wp[l + 32];
    const float* a = ga + hh * 2 * HD;
    float s = v0 * a[l] + v1 * a[l + 32];
    float d = v0 * a[HD + l] + v1 * a[HD + l + 32];
    s = warpSum(s);
    d = warpSum(d);
    if (l == 0) { g_src[hh * T_N + n] = s; g_dst[hh * T_N + n] = d; }
}

__global__ void __launch_bounds__(256) dmax_k()
{
    int h = blockIdx.x;
    float m = -1e30f;
    for (int i = threadIdx.x; i < T_N; i += 256) m = fmaxf(m, g_dst[h * T_N + i]);
    __shared__ float sh[8];
    int w = threadIdx.x >> 5, l = threadIdx.x & 31;
    m = warpMax(m);
    if (l == 0) sh[w] = m;
    __syncthreads();
    if (threadIdx.x == 0) {
        float mm = sh[0];
        #pragma unroll
        for (int i = 1; i < 8; i++) mm = fmaxf(mm, sh[i]);
        g_dmax[h] = mm;
    }
}

// ============== attention + fused combine: one CTA = (128 rows, 1 head) ==============
__global__ void __launch_bounds__(256) attn_tc(const int* __restrict__ adj)
{
    extern __shared__ char dsm[];
    uint32_t raw = s2u(dsm);
    uint32_t base = (raw + 1023u) & ~1023u;
    char* smc = dsm + (base - raw);
    float* zfin = (float*)(smc + SM_ZF);

    int tid = threadIdx.x, w = tid >> 5, lane = tid & 31;
    int h = blockIdx.x & 3;
    int i0 = (blockIdx.x >> 2) * 128;

    const float L2E = 1.44269504f;
    float srcv[16], mlog[16], zacc[16];   // srcv/mlog pre-scaled by log2(e)
    float dmax = g_dmax[h];
    #pragma unroll
    for (int i = 0; i < 16; i++) {
        float s = g_src[h * T_N + i0 + w * 16 + i];
        float m = s + dmax;
        m = fmaxf(m, 0.2f * m);
        srcv[i] = s * L2E;
        mlog[i] = m * L2E;
        zacc[i] = 0.f;
    }
    const float* whp0 = g_Wh + h * 64;

#if HAS_TC
    if (w == 0)
        asm volatile("tcgen05.alloc.cta_group::1.sync.aligned.shared::cta.b32 [%0], %1;"
                     :: "r"(base + SM_TPTR), "r"(64u) : "memory");
    if (tid == 0) { mbar_init(base + SM_MB0, 1); mbar_init(base + SM_MB1, 1); }
    __syncthreads();
    uint32_t tmem;
    asm volatile("ld.shared.b32 %0, [%1];" : "=r"(tmem) : "r"(base + SM_TPTR));

    const int2*   a2p = (const int2*)(adj + (size_t)(i0 + w * 16) * T_N) + lane;
    const float2* d2p = (const float2*)(g_dst + h * T_N) + lane;

    int wp0 = 0, wp1 = 0;
    const int NT = T_N / 64;

    for (int t = 0; t < NT; t++) {
        int buf = t & 1;
        int j0 = t * 64;
        uint32_t Pb = buf ? SM_P1 : SM_P0;
        uint32_t Bb = buf ? SM_B1 : SM_B0;
        uint32_t mb = base + (buf ? SM_MB1 : SM_MB0);

        if (t >= 2) {
            if (buf == 0) { mbar_wait(base + SM_MB0, wp0); wp0 ^= 1; }
            else          { mbar_wait(base + SM_MB1, wp1); wp1 ^= 1; }
        }

        // issue this tile's adj/dst loads first (B-stage hides their latency)
        int2 av[16];
        #pragma unroll
        for (int i = 0; i < 16; i++) av[i] = a2p[(size_t)i * (T_N / 2) + t * 32];
        float2 d2 = d2p[t * 32];
        float dx = d2.x * L2E, dy = d2.y * L2E;

        // B tile: Bs[n][k] = Wh[j0+k][h*64+n], 2 chunks of 32 k, raw fp32 (tf32 truncation)
        #pragma unroll
        for (int q = 0; q < 16; q++) {
            int idx = tid + q * 256;
            int n = idx & 63, k = idx >> 6;
            float v = whp0[(size_t)(j0 + k) * HID + n];
            uint32_t off = Bb + ((k >> 5) << 13) + sw128((uint32_t)(n * 128 + (k & 31) * 4));
            *(float*)(smc + off) = v;
        }

        // P tile: lane owns j-pair (2*lane, 2*lane+1)
        uint32_t chunkoff = Pb + ((uint32_t)(lane >> 4) << 14);
        uint32_t col4 = (uint32_t)(((2 * lane) & 31) * 4);
        #pragma unroll
        for (int i = 0; i < 16; i++) {
            int row = w * 16 + i;
            float e0 = srcv[i] + dx;
            float e1 = srcv[i] + dy;
            e0 = fmaxf(e0, 0.2f * e0);
            e1 = fmaxf(e1, 0.2f * e1);
            float p0 = ex2f(e0 - mlog[i]);
            float p1 = ex2f(e1 - mlog[i]);
            p0 = av[i].x ? p0 : 0.f;
            p1 = av[i].y ? p1 : 0.f;
            zacc[i] += p0 + p1;
            *(float2*)(smc + chunkoff + sw128((uint32_t)(row * 128) + col4)) =
                make_float2(p0, p1);
        }

        asm volatile("fence.proxy.async.shared::cta;" ::: "memory");
        __syncthreads();

        if (w == 0 && elect_one()) {
            #pragma unroll
            for (int c2 = 0; c2 < 2; c2++) {
                uint64_t ad = DESC_BASE | ((uint64_t)((base + Pb + c2 * 16384) >> 4) & 0x3FFF);
                uint64_t bd = DESC_BASE | ((uint64_t)((base + Bb + c2 * 8192) >> 4) & 0x3FFF);
                #pragma unroll
                for (int c = 0; c < 4; c++)
                    mma_tf32_ss(tmem, ad + c * 2, bd + c * 2, TF32_IDESC,
                                (t > 0 || c2 > 0 || c > 0) ? 1u : 0u);
            }
            tc_commit(mb);
        }
    }

    #pragma unroll
    for (int i = 0; i < 16; i++) {
        float z = warpSum(zacc[i]);
        if (lane == i) zfin[w * 16 + i] = 1.f / z;
    }
    __syncthreads();

    mbar_wait(base + SM_MB1, wp1);
    asm volatile("tcgen05.fence::after_thread_sync;" ::: "memory");

    // epilogue: normalize + fused residual combine into g_h
    if (w < 4) {
        uint32_t dr[64];
        TC_LD_X32(dr, tmem);
        TC_LD_X32(dr + 32, tmem + 32);
        asm volatile("tcgen05.wait::ld.sync.aligned;" ::: "memory");
        int row = w * 32 + lane;
        float zi = zfin[row];
        float4* hp = (float4*)&g_h[(size_t)(i0 + row) * HID + h * 64];
        #pragma unroll
        for (int q = 0; q < 16; q++) {
            float4 old = hp[q];
            float4 o;
            o.x = 0.5f * fmaxf(__uint_as_float(dr[4 * q])     * zi, 0.f) + 0.5f * old.x;
            o.y = 0.5f * fmaxf(__uint_as_float(dr[4 * q + 1]) * zi, 0.f) + 0.5f * old.y;
            o.z = 0.5f * fmaxf(__uint_as_float(dr[4 * q + 2]) * zi, 0.f) + 0.5f * old.z;
            o.w = 0.5f * fmaxf(__uint_as_float(dr[4 * q + 3]) * zi, 0.f) + 0.5f * old.w;
            hp[q] = o;
        }
    }
    __syncthreads();
    if (w == 0) {
        asm volatile("tcgen05.relinquish_alloc_permit.cta_group::1.sync.aligned;");
        asm volatile("tcgen05.dealloc.cta_group::1.sync.aligned.b32 %0, %1;"
                     :: "r"(tmem), "r"(64u));
    }
#else
    // -------- SIMT fallback (non-sm_103a passes only) --------
    float* P = (float*)smc;     // [128][33]
    int col = tid & 63, rhalf = tid >> 6;
    float acc[32];
    #pragma unroll
    for (int r = 0; r < 32; r++) acc[r] = 0.f;

    const int* adjp = adj + (size_t)(i0 + w * 16) * T_N + lane;
    const float* dstp = g_dst + h * T_N + lane;
    __syncthreads();

    for (int t = 0; t < T_N / 32; t++) {
        int j0 = t * 32;
        float dl = dstp[j0] * L2E;
        #pragma unroll
        for (int i = 0; i < 16; i++) {
            int avi = adjp[(size_t)i * T_N + j0];
            float ev = srcv[i] + dl;
            ev = fmaxf(ev, 0.2f * ev);
            float p = ex2f(ev - mlog[i]);
            p = avi ? p : 0.f;
            zacc[i] += p;
            P[(w * 16 + i) * 33 + lane] = p;
        }
        __syncthreads();
        const float* whc = whp0 + (size_t)j0 * HID + col;
        #pragma unroll 4
        for (int jl = 0; jl < 32; jl++) {
            float b = whc[(size_t)jl * HID];
            const float* Pc = P + (rhalf * 32) * 33 + jl;
            #pragma unroll
            for (int r = 0; r < 32; r++) acc[r] += Pc[r * 33] * b;
        }
        __syncthreads();
    }

    #pragma unroll
    for (int i = 0; i < 16; i++) {
        float z = warpSum(zacc[i]);
        if (lane == i) zfin[w * 16 + i] = 1.f / z;
    }
    __syncthreads();
    #pragma unroll
    for (int r = 0; r < 32; r++) {
        int row = rhalf * 32 + r;
        size_t gi = (size_t)(i0 + row) * HID + h * 64 + col;
        float o = acc[r] * zfin[row];
        g_h[gi] = 0.5f * fmaxf(o, 0.f) + 0.5f * g_h[gi];
    }
#endif
}

__global__ void __launch_bounds__(256) scorecos_k()
{
    __shared__ float q[HID];
    int tid = threadIdx.x;
    q[tid] = g_h[tid];
    __syncthreads();
    int w = tid >> 5, l = tid & 31;
    int j = blockIdx.x * 8 + w;
    if (j >= NS) return;
    const float* s = &g_h[(size_t)(S0 + j) * HID];
    float qs = 0.f, ss = 0.f;
    #pragma unroll
    for (int e = 0; e < 8; e++) {
        float x = s[l + 32 * e];
        qs += q[l + 32 * e] * x;
        ss += x * x;
    }
    qs = warpSum(qs);
    ss = warpSum(ss);
    if (l == 0) {
        g_scores[j] = qs * (1.0f / 16.0f);
        g_cosf[j] = qs * g_scal[1] / (sqrtf(ss) + 1e-8f);
    }
}

__global__ void __launch_bounds__(1024) softmax_k()
{
    __shared__ float sh[32];
    int tid = threadIdx.x, w = tid >> 5, l = tid & 31;

    float m = -1e30f;
    for (int i = tid; i < NS; i += 1024) m = fmaxf(m, g_scores[i]);
    m = warpMax(m);
    if (l == 0) sh[w] = m;
    __syncthreads();
    if (w == 0) { float mm = sh[l]; mm = warpMax(mm); if (l == 0) sh[0] = mm; }
    __syncthreads();
    m = sh[0];
    __syncthreads();

    float sum = 0.f;
    for (int i = tid; i < NS; i += 1024) {
        float e = __expf(g_scores[i] - m);
        g_aw[i] = e;
        sum += e;
    }
    sum = warpSum(sum);
    if (l == 0) sh[w] = sum;
    __syncthreads();
    if (w == 0) { float ss = sh[l]; ss = warpSum(ss); if (l == 0) sh[0] = ss; }
    __syncthreads();
    float inv = 1.f / sh[0];
    for (int i = tid; i < NS; i += 1024) g_aw[i] *= inv;
}

__global__ void __launch_bounds__(256) fusion_k(const float* __restrict__ fw,
                                                const float* __restrict__ fb,
                                                const float* __restrict__ ow,
                                                const float* __restrict__ obp,
                                                float* __restrict__ out)
{
    __shared__ float fws[256][33];
    __shared__ __align__(16) float feat_s[32][20];
    __shared__ float awv[16], cosv[16];
    __shared__ float red2[16][8];
    int tid = threadIdx.x;
    int w = tid >> 5, lane = tid & 31;
    int j0 = blockIdx.x * 16;

    if (tid < 16) {
        int j = j0 + tid;
        awv[tid]  = (j < NS) ? g_aw[j]   : 0.f;
        cosv[tid] = (j < NS) ? g_cosf[j] : 0.f;
    }
    __syncthreads();

    unsigned long long acc2[8];
    #pragma unroll
    for (int i = 0; i < 8; i++) acc2[i] = 0ull;
    int c = tid;

    for (int k0 = 0; k0 < 512; k0 += 32) {
        #pragma unroll 8
        for (int rr = 0; rr < 32; rr++)
            fws[w * 32 + rr][lane] = fw[(size_t)(w * 32 + rr) * 514 + k0 + lane];
        #pragma unroll
        for (int q = 0; q < 2; q++) {
            int idx = tid + q * 256;
            int r = idx >> 5, kk = idx & 31;
            int k = k0 + kk;
            int j = j0 + r;
            float v = 0.f;
            if (j < NS) {
                if (k < 256) v = g_h[(size_t)(S0 + j) * HID + k];
                else         v = g_h[k - 256] * (awv[r] + 0.5f);
            }
            feat_s[kk][r] = v;
        }
        __syncthreads();

        #pragma unroll 8
        for (int kk = 0; kk < 32; kk++) {
            float wv = fws[c][kk];
            unsigned long long wvd;
            asm("mov.b64 %0, {%1,%1};" : "=l"(wvd) : "r"(__float_as_uint(wv)));
            const ulonglong2* fp = (const ulonglong2*)&feat_s[kk][0];
            #pragma unroll
            for (int q = 0; q < 4; q++) {
                ulonglong2 fv = fp[q];
                asm("fma.rn.f32x2 %0, %1, %2, %0;" : "+l"(acc2[2*q  ]) : "l"(fv.x), "l"(wvd));
                asm("fma.rn.f32x2 %0, %1, %2, %0;" : "+l"(acc2[2*q+1]) : "l"(fv.y), "l"(wvd));
            }
        }
        __syncthreads();
    }

    float acc[16];
    #pragma unroll
    for (int q = 0; q < 8; q++) {
        acc[2*q]   = __uint_as_float((unsigned)(acc2[q] & 0xffffffffull));
        acc[2*q+1] = __uint_as_float((unsigned)(acc2[q] >> 32));
    }
    float w512 = fw[(size_t)c * 514 + 512];
    float w513 = fw[(size_t)c * 514 + 513];
    #pragma unroll
    for (int r = 0; r < 16; r++) acc[r] += w512 * cosv[r] + w513 * awv[r];

    float fbv = fb[c];
    float owv = ow[c];
    #pragma unroll
    for (int r = 0; r < 16; r++) {
        float gv = fmaxf(acc[r] + fbv, 0.f) * owv;
        gv = warpSum(gv);
        if (lane == 0) red2[r][w] = gv;
    }
    __syncthreads();
    if (tid < 16) {
        float s = 0.f;
        #pragma unroll
        for (int ww = 0; ww < 8; ww++) s += red2[tid][ww];
        int j = j0 + tid;
        if (j < NS) out[j] = s + obp[0] + 0.5f * cosv[tid];
    }
}

// ---------------- launch ----------------
extern "C" void kernel_launch(void* const* d_in, const int* in_sizes, int n_in,
                              void* d_out, int out_size)
{
    const float* emb    = (const float*)d_in[0];
    const int*   adj    = (const int*)  d_in[1];
    const float* proj_w = (const float*)d_in[3];
    const float* proj_b = (const float*)d_in[4];
    const float* ln_s   = (const float*)d_in[5];
    const float* ln_b   = (const float*)d_in[6];
    const float* gat_W  = (const float*)d_in[7];
    const float* gat_a  = (const float*)d_in[8];
    const float* fw     = (const float*)d_in[9];
    const float* fb     = (const float*)d_in[10];
    const float* ow     = (const float*)d_in[11];
    const float* ob     = (const float*)d_in[12];
    float* out = (float*)d_out;

    float *hP, *xP, *whP;
    cudaGetSymbolAddress((void**)&hP,  g_h);
    cudaGetSymbolAddress((void**)&xP,  g_x);
    cudaGetSymbolAddress((void**)&whP, g_Wh);

    cudaFuncSetAttribute(attn_tc, cudaFuncAttributeMaxDynamicSharedMemorySize, SM_TOTAL);

    gemm16<<<T_N / 16, 256>>>(emb, proj_w, proj_b, hP, EMB, 1);
    rownorm0<<<1, 256>>>(0);
    cos_update<<<(NS + 7) / 8, 256>>>();

    for (int L = 0; L < 2; L++) {
        ln2_k<<<T_N / 8, 256>>>(ln_s + L * HID, ln_b + L * HID);
        gemm16<<<T_N / 16, 256>>>(xP, gat_W + (size_t)L * HID * HID, nullptr, whP, HID, 0);
        srcdst_k<<<T_N * NH / 8, 256>>>(gat_a + L * NH * 2 * HD);
        dmax_k<<<NH, 256>>>();
        attn_tc<<<128, 256, SM_TOTAL>>>(adj);
    }

    rownorm0<<<1, 256>>>(1);
    scorecos_k<<<(NS + 7) / 8, 256>>>();
    softmax_k<<<1, 1024>>>();
    fusion_k<<<(NS + 15) / 16, 256>>>(fw, fb, ow, ob, out);
}

// round 7
// speedup vs baseline: 1.4045x; 1.4045x over previous
#include <cuda_runtime.h>
#include <math.h>
#include <cstdint>

#define T_N  4096
#define EMB  384
#define HID  256
#define NH   4
#define HD   64
#define MD   32
#define S0   33
#define NS   4063

#if defined(__CUDA_ARCH_FEAT_SM103_ALL) || defined(__CUDA_ARCH_FEAT_SM100_ALL) || defined(__CUDA_ARCH_FEAT_SM101_ALL)
#define HAS_TC 1
#else
#define HAS_TC 0
#endif

__device__ float g_h  [T_N * HID];
__device__ float g_x  [T_N * HID];
__device__ float g_Wh [T_N * HID];
__device__ float g_src[NH * T_N];
__device__ float g_dst[NH * T_N];
__device__ float g_dmax[NH];
__device__ float g_scal[4];
__device__ float g_scores[NS];
__device__ float g_cosf[NS];
__device__ float g_aw[NS];

__device__ __forceinline__ float warpSum(float v) {
    #pragma unroll
    for (int o = 16; o; o >>= 1) v += __shfl_xor_sync(0xffffffffu, v, o);
    return v;
}
__device__ __forceinline__ float warpMax(float v) {
    #pragma unroll
    for (int o = 16; o; o >>= 1) v = fmaxf(v, __shfl_xor_sync(0xffffffffu, v, o));
    return v;
}
__device__ float blockSum256(float v) {
    __shared__ float sh[8];
    int w = threadIdx.x >> 5, l = threadIdx.x & 31;
    v = warpSum(v);
    if (l == 0) sh[w] = v;
    __syncthreads();
    float s = (threadIdx.x < 8) ? sh[threadIdx.x] : 0.f;
    if (w == 0) { s = warpSum(s); if (l == 0) sh[0] = s; }
    __syncthreads();
    float r = sh[0];
    __syncthreads();
    return r;
}

__device__ __forceinline__ uint32_t s2u(const void* p) {
    uint32_t a;
    asm("{ .reg .u64 t; cvta.to.shared.u64 t, %1; cvt.u32.u64 %0, t; }"
        : "=r"(a) : "l"(p));
    return a;
}
__device__ __forceinline__ uint32_t sw128(uint32_t off) {
    return off ^ ((off >> 3) & 0x70);
}
__device__ __forceinline__ float ex2f(float x) {
    float r;
    asm("ex2.approx.f32 %0, %1;" : "=f"(r) : "f"(x));
    return r;
}

#if HAS_TC
__device__ __forceinline__ uint32_t elect_one() {
    uint32_t pred;
    asm volatile("{\n\t.reg .pred p;\n\telect.sync _|p, 0xFFFFFFFF;\n\t"
                 "selp.b32 %0, 1, 0, p;\n\t}" : "=r"(pred));
    return pred;
}
__device__ __forceinline__ void mbar_init(uint32_t addr, uint32_t cnt) {
    asm volatile("mbarrier.init.shared.b64 [%0], %1;" :: "r"(addr), "r"(cnt) : "memory");
}
__device__ __forceinline__ void mbar_wait(uint32_t addr, uint32_t parity) {
    asm volatile(
        "{\n\t.reg .pred P;\n\t"
        "WL%=:\n\t"
        "mbarrier.try_wait.parity.acquire.cta.shared::cta.b64 P, [%0], %1, 0x989680;\n\t"
        "@P bra WD%=;\n\t"
        "bra WL%=;\n\t"
        "WD%=:\n\t}"
        :: "r"(addr), "r"(parity) : "memory");
}
__device__ __forceinline__ void sts_tf32(uint32_t addr, float v) {
    uint32_t t;
    asm("cvt.rn.tf32.f32 %0, %1;" : "=r"(t) : "f"(v));
    asm volatile("st.shared.b32 [%0], %1;" :: "r"(addr), "r"(t) : "memory");
}
__device__ __forceinline__ void mma_tf32_ss(uint32_t d_tmem, uint64_t a_desc,
                                            uint64_t b_desc, uint32_t idesc,
                                            uint32_t en) {
    asm volatile(
        "{\n\t.reg .pred p;\n\tsetp.ne.u32 p, %4, 0;\n\t"
        "tcgen05.mma.cta_group::1.kind::tf32 [%0], %1, %2, %3, {%5, %5, %5, %5}, p;\n\t}"
        :: "r"(d_tmem), "l"(a_desc), "l"(b_desc), "r"(idesc), "r"(en), "r"(0u)
        : "memory");
}
__device__ __forceinline__ void tc_commit(uint32_t mbar) {
    asm volatile(
        "tcgen05.commit.cta_group::1.mbarrier::arrive::one.shared::cluster.b64 [%0];"
        :: "r"(mbar) : "memory");
}
#define TC_LD_X32(r, tmem_addr) \
    asm volatile( \
        "tcgen05.ld.sync.aligned.32x32b.x32.b32 " \
        "{%0, %1, %2, %3, %4, %5, %6, %7, " \
        " %8, %9, %10, %11, %12, %13, %14, %15, " \
        " %16, %17, %18, %19, %20, %21, %22, %23, " \
        " %24, %25, %26, %27, %28, %29, %30, %31}, [%32];" \
        : "=r"((r)[0]),  "=r"((r)[1]),  "=r"((r)[2]),  "=r"((r)[3]), \
          "=r"((r)[4]),  "=r"((r)[5]),  "=r"((r)[6]),  "=r"((r)[7]), \
          "=r"((r)[8]),  "=r"((r)[9]),  "=r"((r)[10]), "=r"((r)[11]), \
          "=r"((r)[12]), "=r"((r)[13]), "=r"((r)[14]), "=r"((r)[15]), \
          "=r"((r)[16]), "=r"((r)[17]), "=r"((r)[18]), "=r"((r)[19]), \
          "=r"((r)[20]), "=r"((r)[21]), "=r"((r)[22]), "=r"((r)[23]), \
          "=r"((r)[24]), "=r"((r)[25]), "=r"((r)[26]), "=r"((r)[27]), \
          "=r"((r)[28]), "=r"((r)[29]), "=r"((r)[30]), "=r"((r)[31]) \
        : "r"(tmem_addr))
#endif // HAS_TC

// smem desc: SW128, version=1, SBO=64, LBO=1
#define DESC_BASE ((2ull << 61) | (1ull << 46) | (64ull << 32) | (1ull << 16))
// idesc: dtype=F32, atype=TF32, btype=TF32, N=64, M=128
#define TF32_IDESC ((1u << 4) | (2u << 7) | (2u << 10) | (8u << 17) | (8u << 24))

// R5 layout: P buf = 128 x 128B = 16KB, B buf = 64 x 128B = 8KB, two of each
#define SM_P0    0
#define SM_P1    16384
#define SM_B0    32768
#define SM_B1    40960
#define SM_TPTR  49152
#define SM_MB0   49168
#define SM_MB1   49176
#define SM_ZF    49184
#define SM_TOTAL (49184 + 512 + 1024)

// ======================= generic 16-row GEMM (FFMA2) =======================
#define GEMM_STEP2(WV, KK)                                                    \
    {                                                                         \
        unsigned long long w2;                                                \
        asm("mov.b64 %0, {%1,%1};" : "=l"(w2) : "r"(__float_as_uint(WV)));    \
        const ulonglong2* av = (const ulonglong2*)&sa[(KK) * 16];             \
        ulonglong2 a0 = av[0], a1 = av[1];                                    \
        asm("fma.rn.f32x2 %0, %1, %2, %0;" : "+l"(acc2[0]) : "l"(a0.x), "l"(w2)); \
        asm("fma.rn.f32x2 %0, %1, %2, %0;" : "+l"(acc2[1]) : "l"(a0.y), "l"(w2)); \
        asm("fma.rn.f32x2 %0, %1, %2, %0;" : "+l"(acc2[2]) : "l"(a1.x), "l"(w2)); \
        asm("fma.rn.f32x2 %0, %1, %2, %0;" : "+l"(acc2[3]) : "l"(a1.y), "l"(w2)); \
        ulonglong2 a2 = av[2], a3 = av[3];                                    \
        asm("fma.rn.f32x2 %0, %1, %2, %0;" : "+l"(acc2[4]) : "l"(a2.x), "l"(w2)); \
        asm("fma.rn.f32x2 %0, %1, %2, %0;" : "+l"(acc2[5]) : "l"(a2.y), "l"(w2)); \
        asm("fma.rn.f32x2 %0, %1, %2, %0;" : "+l"(acc2[6]) : "l"(a3.x), "l"(w2)); \
        asm("fma.rn.f32x2 %0, %1, %2, %0;" : "+l"(acc2[7]) : "l"(a3.y), "l"(w2)); \
    }

__global__ void __launch_bounds__(256) gemm16(const float* __restrict__ A,
                                              const float* __restrict__ Wt,
                                              const float* __restrict__ bias,
                                              float* __restrict__ Cout,
                                              int K, int doRelu)
{
    __shared__ __align__(16) float sa[EMB * 16];
    int r0 = blockIdx.x * 16;
    for (int idx = threadIdx.x; idx < 16 * K; idx += 256) {
        int r = idx / K, k = idx - r * K;
        sa[k * 16 + r] = A[(size_t)(r0 + r) * K + k];
    }
    __syncthreads();
    unsigned long long acc2[8];
    #pragma unroll
    for (int p = 0; p < 8; p++) acc2[p] = 0ull;
    int c = threadIdx.x;
    const float4* w4 = (const float4*)(Wt + (size_t)c * K);
    int K4 = K >> 2;
    for (int k4 = 0; k4 < K4; k4++) {
        float4 w = w4[k4];
        int kb = k4 * 4;
        GEMM_STEP2(w.x, kb + 0)
        GEMM_STEP2(w.y, kb + 1)
        GEMM_STEP2(w.z, kb + 2)
        GEMM_STEP2(w.w, kb + 3)
    }
    float b = bias ? bias[c] : 0.f;
    #pragma unroll
    for (int p = 0; p < 8; p++) {
        float lo = __uint_as_float((unsigned)(acc2[p] & 0xffffffffull)) + b;
        float hi = __uint_as_float((unsigned)(acc2[p] >> 32)) + b;
        if (doRelu) { lo = fmaxf(lo, 0.f); hi = fmaxf(hi, 0.f); }
        Cout[(size_t)(r0 + 2 * p)     * HID + c] = lo;
        Cout[(size_t)(r0 + 2 * p + 1) * HID + c] = hi;
    }
}

__global__ void __launch_bounds__(256) rownorm0(int slot)
{
    float v = g_h[threadIdx.x];
    float s = blockSum256(v * v);
    if (threadIdx.x == 0) g_scal[slot] = 1.f / (sqrtf(s) + 1e-8f);
}

__global__ void __launch_bounds__(256) cos_update()
{
    __shared__ float q[HID];
    int tid = threadIdx.x;
    q[tid] = g_h[tid];
    __syncthreads();
    int w = tid >> 5, l = tid & 31;
    int j = blockIdx.x * 8 + w;
    if (j >= NS) return;
    float* s = &g_h[(size_t)(S0 + j) * HID];
    float sv[8];
    float qs = 0.f, ss = 0.f;
    #pragma unroll
    for (int e = 0; e < 8; e++) {
        float x = s[l + 32 * e];
        sv[e] = x;
        qs += q[l + 32 * e] * x;
        ss += x * x;
    }
    qs = warpSum(qs);
    ss = warpSum(ss);
    float cs = qs * g_scal[0] / (sqrtf(ss) + 1e-8f);
    #pragma unroll
    for (int e = 0; e < 8; e++)
        s[l + 32 * e] = sv[e] + 0.8f * q[l + 32 * e] * cs;
}

// warp-per-row layernorm
__global__ void __launch_bounds__(256) ln2_k(const float* __restrict__ scale,
                                             const float* __restrict__ bias)
{
    __shared__ float sc[HID], bi[HID];
    int tid = threadIdx.x, w = tid >> 5, l = tid & 31;
    sc[tid] = scale[tid];
    bi[tid] = bias[tid];
    __syncthreads();
    int row = blockIdx.x * 8 + w;
    const float* hp = &g_h[(size_t)row * HID];
    float v[8];
    float s = 0.f;
    #pragma unroll
    for (int e = 0; e < 8; e++) { v[e] = hp[l + 32 * e]; s += v[e]; }
    float mu = warpSum(s) * (1.f / HID);
    float ss = 0.f;
    #pragma unroll
    for (int e = 0; e < 8; e++) { v[e] -= mu; ss += v[e] * v[e]; }
    float rs = rsqrtf(warpSum(ss) * (1.f / HID) + 1e-5f);
    float* xp = &g_x[(size_t)row * HID];
    #pragma unroll
    for (int e = 0; e < 8; e++)
        xp[l + 32 * e] = v[e] * rs * sc[l + 32 * e] + bi[l + 32 * e];
}

__global__ void __launch_bounds__(256) srcdst_k(const float* __restrict__ ga)
{
    int w = threadIdx.x >> 5, l = threadIdx.x & 31;
    int gid = blockIdx.x * 8 + w;
    int n = gid >> 2, hh = gid & 3;
    const float* wp = &g_Wh[(size_t)n * HID + hh * HD];
    float v0 = wp[l], v1 = wp[l + 32];
    const float* a = ga + hh * 2 * HD;
    float s = v0 * a[l] + v1 * a[l + 32];
    float d = v0 * a[HD + l] + v1 * a[HD + l + 32];
    s = warpSum(s);
    d = warpSum(d);
    if (l == 0) { g_src[hh * T_N + n] = s; g_dst[hh * T_N + n] = d; }
}

__global__ void __launch_bounds__(256) dmax_k()
{
    int h = blockIdx.x;
    float m = -1e30f;
    for (int i = threadIdx.x; i < T_N; i += 256) m = fmaxf(m, g_dst[h * T_N + i]);
    __shared__ float sh[8];
    int w = threadIdx.x >> 5, l = threadIdx.x & 31;
    m = warpMax(m);
    if (l == 0) sh[w] = m;
    __syncthreads();
    if (threadIdx.x == 0) {
        float mm = sh[0];
        #pragma unroll
        for (int i = 1; i < 8; i++) mm = fmaxf(mm, sh[i]);
        g_dmax[h] = mm;
    }
}

// ============== attention (R5 structure) + fused combine epilogue ==============
__global__ void __launch_bounds__(256) attn_tc(const int* __restrict__ adj)
{
    extern __shared__ char dsm[];
    uint32_t raw = s2u(dsm);
    uint32_t base = (raw + 1023u) & ~1023u;
    char* smc = dsm + (base - raw);
    float* zfin = (float*)(smc + SM_ZF);

    int tid = threadIdx.x, w = tid >> 5, lane = tid & 31;
    int h = blockIdx.x & 3;
    int i0 = (blockIdx.x >> 2) * 128;

    const float L2E = 1.44269504f;
    float srcv[16], mlog[16], zacc[16];
    float dmax = g_dmax[h];
    #pragma unroll
    for (int i = 0; i < 16; i++) {
        float s = g_src[h * T_N + i0 + w * 16 + i];
        float m = s + dmax;
        m = fmaxf(m, 0.2f * m);
        srcv[i] = s;
        mlog[i] = m * L2E;
        zacc[i] = 0.f;
    }

    const int* adjp = adj + (size_t)(i0 + w * 16) * T_N + lane;
    const float* dstp = g_dst + h * T_N + lane;
    const float* whp0 = g_Wh + h * 64;
    const int NT = T_N / 32;

    int av[16];
    float dval;
    #pragma unroll
    for (int i = 0; i < 16; i++) av[i] = adjp[(size_t)i * T_N];
    dval = dstp[0];

#if HAS_TC
    if (w == 0)
        asm volatile("tcgen05.alloc.cta_group::1.sync.aligned.shared::cta.b32 [%0], %1;"
                     :: "r"(base + SM_TPTR), "r"(64u) : "memory");
    if (tid == 0) { mbar_init(base + SM_MB0, 1); mbar_init(base + SM_MB1, 1); }
    __syncthreads();
    uint32_t tmem;
    asm volatile("ld.shared.b32 %0, [%1];" : "=r"(tmem) : "r"(base + SM_TPTR));

    int wp0 = 0, wp1 = 0;

    for (int t = 0; t < NT; t++) {
        int buf = t & 1;
        int j0 = t * 32;
        uint32_t Pb = base + (buf ? SM_P1 : SM_P0);
        uint32_t Bb = base + (buf ? SM_B1 : SM_B0);
        uint32_t mb = base + (buf ? SM_MB1 : SM_MB0);

        if (t >= 2) {
            if (buf == 0) { mbar_wait(base + SM_MB0, wp0); wp0 ^= 1; }
            else          { mbar_wait(base + SM_MB1, wp1); wp1 ^= 1; }
        }

        // B tile: Bs[n][k] = Wh[j0+k][h*64+n]  (64 x 32 tf32, SW128)
        #pragma unroll
        for (int q = 0; q < 8; q++) {
            int idx = tid + q * 256;
            int n = idx & 63, k = idx >> 6;
            float v = whp0[(size_t)(j0 + k) * HID + n];
            sts_tf32(Bb + sw128((uint32_t)(n * 128 + k * 4)), v);
        }

        // P tile: rows w*16..+15, j = j0+lane (prefetched adj/dst)
        #pragma unroll
        for (int i = 0; i < 16; i++) {
            float ev = srcv[i] + dval;
            ev = fmaxf(ev, 0.2f * ev);
            float wv = ex2f(fmaf(ev, L2E, -mlog[i]));
            wv = av[i] ? wv : 0.f;
            zacc[i] += wv;
            sts_tf32(Pb + sw128((uint32_t)((w * 16 + i) * 128 + lane * 4)), wv);
        }

        if (t < NT - 1) {
            #pragma unroll
            for (int i = 0; i < 16; i++) av[i] = adjp[(size_t)i * T_N + j0 + 32];
            dval = dstp[j0 + 32];
        }

        asm volatile("fence.proxy.async.shared::cta;" ::: "memory");
        __syncthreads();

        if (w == 0 && elect_one()) {
            uint64_t ad = DESC_BASE | ((uint64_t)(Pb >> 4) & 0x3FFF);
            uint64_t bd = DESC_BASE | ((uint64_t)(Bb >> 4) & 0x3FFF);
            #pragma unroll
            for (int c = 0; c < 4; c++)
                mma_tf32_ss(tmem, ad + c * 2, bd + c * 2, TF32_IDESC,
                            (t > 0 || c > 0) ? 1u : 0u);
            tc_commit(mb);
        }
    }

    #pragma unroll
    for (int i = 0; i < 16; i++) {
        float z = warpSum(zacc[i]);
        if (lane == i) zfin[w * 16 + i] = 1.f / z;
    }
    __syncthreads();

    mbar_wait(base + SM_MB1, wp1);
    asm volatile("tcgen05.fence::after_thread_sync;" ::: "memory");

    // epilogue: normalize + fused residual combine into g_h
    if (w < 4) {
        uint32_t dr[64];
        TC_LD_X32(dr, tmem);
        TC_LD_X32(dr + 32, tmem + 32);
        asm volatile("tcgen05.wait::ld.sync.aligned;" ::: "memory");
        int row = w * 32 + lane;
        float zi = zfin[row];
        float4* hp = (float4*)&g_h[(size_t)(i0 + row) * HID + h * 64];
        #pragma unroll
        for (int q = 0; q < 16; q++) {
            float4 old = hp[q];
            float4 o;
            o.x = 0.5f * fmaxf(__uint_as_float(dr[4 * q])     * zi, 0.f) + 0.5f * old.x;
            o.y = 0.5f * fmaxf(__uint_as_float(dr[4 * q + 1]) * zi, 0.f) + 0.5f * old.y;
            o.z = 0.5f * fmaxf(__uint_as_float(dr[4 * q + 2]) * zi, 0.f) + 0.5f * old.z;
            o.w = 0.5f * fmaxf(__uint_as_float(dr[4 * q + 3]) * zi, 0.f) + 0.5f * old.w;
            hp[q] = o;
        }
    }
    __syncthreads();
    if (w == 0) {
        asm volatile("tcgen05.relinquish_alloc_permit.cta_group::1.sync.aligned;");
        asm volatile("tcgen05.dealloc.cta_group::1.sync.aligned.b32 %0, %1;"
                     :: "r"(tmem), "r"(64u));
    }
#else
    // -------- SIMT fallback (non-sm_103a passes only) --------
    float* P = (float*)smc;     // [128][33]
    int col = tid & 63, rhalf = tid >> 6;
    float acc[32];
    #pragma unroll
    for (int r = 0; r < 32; r++) acc[r] = 0.f;
    __syncthreads();

    for (int t = 0; t < NT; t++) {
        int j0 = t * 32;
        #pragma unroll
        for (int i = 0; i < 16; i++) {
            float ev = srcv[i] + dval;
            ev = fmaxf(ev, 0.2f * ev);
            float p = ex2f(fmaf(ev, L2E, -mlog[i]));
            p = av[i] ? p : 0.f;
            zacc[i] += p;
            P[(w * 16 + i) * 33 + lane] = p;
        }
        if (t < NT - 1) {
            #pragma unroll
            for (int i = 0; i < 16; i++) av[i] = adjp[(size_t)i * T_N + j0 + 32];
            dval = dstp[j0 + 32];
        }
        __syncthreads();
        const float* whc = whp0 + (size_t)j0 * HID + col;
        #pragma unroll 4
        for (int jl = 0; jl < 32; jl++) {
            float b = whc[(size_t)jl * HID];
            const float* Pc = P + (rhalf * 32) * 33 + jl;
            #pragma unroll
            for (int r = 0; r < 32; r++) acc[r] += Pc[r * 33] * b;
        }
        __syncthreads();
    }

    #pragma unroll
    for (int i = 0; i < 16; i++) {
        float z = warpSum(zacc[i]);
        if (lane == i) zfin[w * 16 + i] = 1.f / z;
    }
    __syncthreads();
    #pragma unroll
    for (int r = 0; r < 32; r++) {
        int row = rhalf * 32 + r;
        size_t gi = (size_t)(i0 + row) * HID + h * 64 + col;
        float o = acc[r] * zfin[row];
        g_h[gi] = 0.5f * fmaxf(o, 0.f) + 0.5f * g_h[gi];
    }
#endif
}

__global__ void __launch_bounds__(256) scorecos_k()
{
    __shared__ float q[HID];
    int tid = threadIdx.x;
    q[tid] = g_h[tid];
    __syncthreads();
    int w = tid >> 5, l = tid & 31;
    int j = blockIdx.x * 8 + w;
    if (j >= NS) return;
    const float* s = &g_h[(size_t)(S0 + j) * HID];
    float qs = 0.f, ss = 0.f;
    #pragma unroll
    for (int e = 0; e < 8; e++) {
        float x = s[l + 32 * e];
        qs += q[l + 32 * e] * x;
        ss += x * x;
    }
    qs = warpSum(qs);
    ss = warpSum(ss);
    if (l == 0) {
        g_scores[j] = qs * (1.0f / 16.0f);
        g_cosf[j] = qs * g_scal[1] / (sqrtf(ss) + 1e-8f);
    }
}

__global__ void __launch_bounds__(1024) softmax_k()
{
    __shared__ float sh[32];
    int tid = threadIdx.x, w = tid >> 5, l = tid & 31;

    float m = -1e30f;
    for (int i = tid; i < NS; i += 1024) m = fmaxf(m, g_scores[i]);
    m = warpMax(m);
    if (l == 0) sh[w] = m;
    __syncthreads();
    if (w == 0) { float mm = sh[l]; mm = warpMax(mm); if (l == 0) sh[0] = mm; }
    __syncthreads();
    m = sh[0];
    __syncthreads();

    float sum = 0.f;
    for (int i = tid; i < NS; i += 1024) {
        float e = __expf(g_scores[i] - m);
        g_aw[i] = e;
        sum += e;
    }
    sum = warpSum(sum);
    if (l == 0) sh[w] = sum;
    __syncthreads();
    if (w == 0) { float ss = sh[l]; ss = warpSum(ss); if (l == 0) sh[0] = ss; }
    __syncthreads();
    float inv = 1.f / sh[0];
    for (int i = tid; i < NS; i += 1024) g_aw[i] *= inv;
}

__global__ void __launch_bounds__(256) fusion_k(const float* __restrict__ fw,
                                                const float* __restrict__ fb,
                                                const float* __restrict__ ow,
                                                const float* __restrict__ obp,
                                                float* __restrict__ out)
{
    __shared__ float fws[256][33];
    __shared__ __align__(16) float feat_s[32][20];
    __shared__ float awv[16], cosv[16];
    __shared__ float red2[16][8];
    int tid = threadIdx.x;
    int w = tid >> 5, lane = tid & 31;
    int j0 = blockIdx.x * 16;

    if (tid < 16) {
        int j = j0 + tid;
        awv[tid]  = (j < NS) ? g_aw[j]   : 0.f;
        cosv[tid] = (j < NS) ? g_cosf[j] : 0.f;
    }
    __syncthreads();

    unsigned long long acc2[8];
    #pragma unroll
    for (int i = 0; i < 8; i++) acc2[i] = 0ull;
    int c = tid;

    for (int k0 = 0; k0 < 512; k0 += 32) {
        #pragma unroll 8
        for (int rr = 0; rr < 32; rr++)
            fws[w * 32 + rr][lane] = fw[(size_t)(w * 32 + rr) * 514 + k0 + lane];
        #pragma unroll
        for (int q = 0; q < 2; q++) {
            int idx = tid + q * 256;
            int r = idx >> 5, kk = idx & 31;
            int k = k0 + kk;
            int j = j0 + r;
            float v = 0.f;
            if (j < NS) {
                if (k < 256) v = g_h[(size_t)(S0 + j) * HID + k];
                else         v = g_h[k - 256] * (awv[r] + 0.5f);
            }
            feat_s[kk][r] = v;
        }
        __syncthreads();

        #pragma unroll 8
        for (int kk = 0; kk < 32; kk++) {
            float wv = fws[c][kk];
            unsigned long long wvd;
            asm("mov.b64 %0, {%1,%1};" : "=l"(wvd) : "r"(__float_as_uint(wv)));
            const ulonglong2* fp = (const ulonglong2*)&feat_s[kk][0];
            #pragma unroll
            for (int q = 0; q < 4; q++) {
                ulonglong2 fv = fp[q];
                asm("fma.rn.f32x2 %0, %1, %2, %0;" : "+l"(acc2[2*q  ]) : "l"(fv.x), "l"(wvd));
                asm("fma.rn.f32x2 %0, %1, %2, %0;" : "+l"(acc2[2*q+1]) : "l"(fv.y), "l"(wvd));
            }
        }
        __syncthreads();
    }

    float acc[16];
    #pragma unroll
    for (int q = 0; q < 8; q++) {
        acc[2*q]   = __uint_as_float((unsigned)(acc2[q] & 0xffffffffull));
        acc[2*q+1] = __uint_as_float((unsigned)(acc2[q] >> 32));
    }
    float w512 = fw[(size_t)c * 514 + 512];
    float w513 = fw[(size_t)c * 514 + 513];
    #pragma unroll
    for (int r = 0; r < 16; r++) acc[r] += w512 * cosv[r] + w513 * awv[r];

    float fbv = fb[c];
    float owv = ow[c];
    #pragma unroll
    for (int r = 0; r < 16; r++) {
        float gv = fmaxf(acc[r] + fbv, 0.f) * owv;
        gv = warpSum(gv);
        if (lane == 0) red2[r][w] = gv;
    }
    __syncthreads();
    if (tid < 16) {
        float s = 0.f;
        #pragma unroll
        for (int ww = 0; ww < 8; ww++) s += red2[tid][ww];
        int j = j0 + tid;
        if (j < NS) out[j] = s + obp[0] + 0.5f * cosv[tid];
    }
}

// ---------------- launch ----------------
extern "C" void kernel_launch(void* const* d_in, const int* in_sizes, int n_in,
                              void* d_out, int out_size)
{
    const float* emb    = (const float*)d_in[0];
    const int*   adj    = (const int*)  d_in[1];
    const float* proj_w = (const float*)d_in[3];
    const float* proj_b = (const float*)d_in[4];
    const float* ln_s   = (const float*)d_in[5];
    const float* ln_b   = (const float*)d_in[6];
    const float* gat_W  = (const float*)d_in[7];
    const float* gat_a  = (const float*)d_in[8];
    const float* fw     = (const float*)d_in[9];
    const float* fb     = (const float*)d_in[10];
    const float* ow     = (const float*)d_in[11];
    const float* ob     = (const float*)d_in[12];
    float* out = (float*)d_out;

    float *hP, *xP, *whP;
    cudaGetSymbolAddress((void**)&hP,  g_h);
    cudaGetSymbolAddress((void**)&xP,  g_x);
    cudaGetSymbolAddress((void**)&whP, g_Wh);

    cudaFuncSetAttribute(attn_tc, cudaFuncAttributeMaxDynamicSharedMemorySize, SM_TOTAL);

    gemm16<<<T_N / 16, 256>>>(emb, proj_w, proj_b, hP, EMB, 1);
    rownorm0<<<1, 256>>>(0);
    cos_update<<<(NS + 7) / 8, 256>>>();

    for (int L = 0; L < 2; L++) {
        ln2_k<<<T_N / 8, 256>>>(ln_s + L * HID, ln_b + L * HID);
        gemm16<<<T_N / 16, 256>>>(xP, gat_W + (size_t)L * HID * HID, nullptr, whP, HID, 0);
        srcdst_k<<<T_N * NH / 8, 256>>>(gat_a + L * NH * 2 * HD);
        dmax_k<<<NH, 256>>>();
        attn_tc<<<128, 256, SM_TOTAL>>>(adj);
    }

    rownorm0<<<1, 256>>>(1);
    scorecos_k<<<(NS + 7) / 8, 256>>>();
    softmax_k<<<1, 1024>>>();
    fusion_k<<<(NS + 15) / 16, 256>>>(fw, fb, ow, ob, out);
}

// round 9
// speedup vs baseline: 1.9699x; 1.4025x over previous
#include <cuda_runtime.h>
#include <math.h>
#include <cstdint>

#define T_N  4096
#define EMB  384
#define HID  256
#define NH   4
#define HD   64
#define MD   32
#define S0   33
#define NS   4063

#if defined(__CUDA_ARCH_FEAT_SM103_ALL) || defined(__CUDA_ARCH_FEAT_SM100_ALL) || defined(__CUDA_ARCH_FEAT_SM101_ALL)
#define HAS_TC 1
#else
#define HAS_TC 0
#endif

__device__ float g_h  [T_N * HID];
__device__ float g_x  [T_N * HID];
__device__ float g_Wh [T_N * HID];
__device__ float g_src[NH * T_N];
__device__ float g_dst[NH * T_N];
__device__ float g_dmax[NH];
__device__ float g_scores[NS];
__device__ float g_cosf[NS];
__device__ float g_aw[NS];

__device__ __forceinline__ float warpSum(float v) {
    #pragma unroll
    for (int o = 16; o; o >>= 1) v += __shfl_xor_sync(0xffffffffu, v, o);
    return v;
}
__device__ __forceinline__ float warpMax(float v) {
    #pragma unroll
    for (int o = 16; o; o >>= 1) v = fmaxf(v, __shfl_xor_sync(0xffffffffu, v, o));
    return v;
}
__device__ float blockSum256(float v) {
    __shared__ float sh[8];
    int w = threadIdx.x >> 5, l = threadIdx.x & 31;
    v = warpSum(v);
    if (l == 0) sh[w] = v;
    __syncthreads();
    float s = (threadIdx.x < 8) ? sh[threadIdx.x] : 0.f;
    if (w == 0) { s = warpSum(s); if (l == 0) sh[0] = s; }
    __syncthreads();
    float r = sh[0];
    __syncthreads();
    return r;
}

__device__ __forceinline__ uint32_t s2u(const void* p) {
    uint32_t a;
    asm("{ .reg .u64 t; cvta.to.shared.u64 t, %1; cvt.u32.u64 %0, t; }"
        : "=r"(a) : "l"(p));
    return a;
}
__device__ __forceinline__ float ex2f(float x) {
    float r;
    asm("ex2.approx.f32 %0, %1;" : "=f"(r) : "f"(x));
    return r;
}

#if HAS_TC
__device__ __forceinline__ uint32_t elect_one() {
    uint32_t pred;
    asm volatile("{\n\t.reg .pred p;\n\telect.sync _|p, 0xFFFFFFFF;\n\t"
                 "selp.b32 %0, 1, 0, p;\n\t}" : "=r"(pred));
    return pred;
}
__device__ __forceinline__ void mbar_init(uint32_t addr, uint32_t cnt) {
    asm volatile("mbarrier.init.shared.b64 [%0], %1;" :: "r"(addr), "r"(cnt) : "memory");
}
__device__ __forceinline__ void mbar_wait(uint32_t addr, uint32_t parity) {
    asm volatile(
        "{\n\t.reg .pred P;\n\t"
        "WL%=:\n\t"
        "mbarrier.try_wait.parity.acquire.cta.shared::cta.b64 P, [%0], %1, 0x989680;\n\t"
        "@P bra WD%=;\n\t"
        "bra WL%=;\n\t"
        "WD%=:\n\t}"
        :: "r"(addr), "r"(parity) : "memory");
}
__device__ __forceinline__ void sts_tf32(uint32_t addr, float v) {
    uint32_t t;
    asm("cvt.rn.tf32.f32 %0, %1;" : "=r"(t) : "f"(v));
    asm volatile("st.shared.b32 [%0], %1;" :: "r"(addr), "r"(t) : "memory");
}
__device__ __forceinline__ void mma_tf32_ss(uint32_t d_tmem, uint64_t a_desc,
                                            uint64_t b_desc, uint32_t idesc,
                                            uint32_t en) {
    asm volatile(
        "{\n\t.reg .pred p;\n\tsetp.ne.u32 p, %4, 0;\n\t"
        "tcgen05.mma.cta_group::1.kind::tf32 [%0], %1, %2, %3, {%5, %5, %5, %5}, p;\n\t}"
        :: "r"(d_tmem), "l"(a_desc), "l"(b_desc), "r"(idesc), "r"(en), "r"(0u)
        : "memory");
}
__device__ __forceinline__ void tc_commit(uint32_t mbar) {
    asm volatile(
        "tcgen05.commit.cta_group::1.mbarrier::arrive::one.shared::cluster.b64 [%0];"
        :: "r"(mbar) : "memory");
}
#define TC_LD_X32(r, tmem_addr) \
    asm volatile( \
        "tcgen05.ld.sync.aligned.32x32b.x32.b32 " \
        "{%0, %1, %2, %3, %4, %5, %6, %7, " \
        " %8, %9, %10, %11, %12, %13, %14, %15, " \
        " %16, %17, %18, %19, %20, %21, %22, %23, " \
        " %24, %25, %26, %27, %28, %29, %30, %31}, [%32];" \
        : "=r"((r)[0]),  "=r"((r)[1]),  "=r"((r)[2]),  "=r"((r)[3]), \
          "=r"((r)[4]),  "=r"((r)[5]),  "=r"((r)[6]),  "=r"((r)[7]), \
          "=r"((r)[8]),  "=r"((r)[9]),  "=r"((r)[10]), "=r"((r)[11]), \
          "=r"((r)[12]), "=r"((r)[13]), "=r"((r)[14]), "=r"((r)[15]), \
          "=r"((r)[16]), "=r"((r)[17]), "=r"((r)[18]), "=r"((r)[19]), \
          "=r"((r)[20]), "=r"((r)[21]), "=r"((r)[22]), "=r"((r)[23]), \
          "=r"((r)[24]), "=r"((r)[25]), "=r"((r)[26]), "=r"((r)[27]), \
          "=r"((r)[28]), "=r"((r)[29]), "=r"((r)[30]), "=r"((r)[31]) \
        : "r"(tmem_addr))
#endif // HAS_TC

// smem desc: SW128, version=1, SBO=64, LBO=1
#define DESC_BASE ((2ull << 61) | (1ull << 46) | (64ull << 32) | (1ull << 16))
// idesc: dtype=F32, atype=TF32, btype=TF32, N=64, M=128
#define TF32_IDESC ((1u << 4) | (2u << 7) | (2u << 10) | (8u << 17) | (8u << 24))

// 4-deep ring: P bufs 4x16KB, B bufs 4x8KB
#define SM_PB(b) ((b) * 16384)
#define SM_BB(b) (65536 + (b) * 8192)
#define SM_TPTR  98304
#define SM_MB(b) (98320 + (b) * 8)
#define SM_ZF    98368
#define SM_TOTAL (98880 + 1024)

// ======================= 16-row GEMM, templated K, coalesced Wt staging =======================
#define GEMM_STEP2(WV, KK)                                                    \
    {                                                                         \
        unsigned long long w2;                                                \
        asm("mov.b64 %0, {%1,%1};" : "=l"(w2) : "r"(__float_as_uint(WV)));    \
        const ulonglong2* av = (const ulonglong2*)&sa[(KK) * 16];             \
        ulonglong2 a0 = av[0], a1 = av[1];                                    \
        asm("fma.rn.f32x2 %0, %1, %2, %0;" : "+l"(acc2[0]) : "l"(a0.x), "l"(w2)); \
        asm("fma.rn.f32x2 %0, %1, %2, %0;" : "+l"(acc2[1]) : "l"(a0.y), "l"(w2)); \
        asm("fma.rn.f32x2 %0, %1, %2, %0;" : "+l"(acc2[2]) : "l"(a1.x), "l"(w2)); \
        asm("fma.rn.f32x2 %0, %1, %2, %0;" : "+l"(acc2[3]) : "l"(a1.y), "l"(w2)); \
        ulonglong2 a2 = av[2], a3 = av[3];                                    \
        asm("fma.rn.f32x2 %0, %1, %2, %0;" : "+l"(acc2[4]) : "l"(a2.x), "l"(w2)); \
        asm("fma.rn.f32x2 %0, %1, %2, %0;" : "+l"(acc2[5]) : "l"(a2.y), "l"(w2)); \
        asm("fma.rn.f32x2 %0, %1, %2, %0;" : "+l"(acc2[6]) : "l"(a3.x), "l"(w2)); \
        asm("fma.rn.f32x2 %0, %1, %2, %0;" : "+l"(acc2[7]) : "l"(a3.y), "l"(w2)); \
    }

template<int K>
__global__ void __launch_bounds__(256) gemm16t(const float* __restrict__ A,
                                               const float* __restrict__ Wt,
                                               const float* __restrict__ bias,
                                               float* __restrict__ Cout,
                                               int doRelu)
{
    extern __shared__ float dyn[];
    float* sa  = dyn;               // [K*16], transposed A tile
    float* fws = dyn + K * 16;      // [256][33] coalesced Wt chunk
    int tid = threadIdx.x, w = tid >> 5, lane = tid & 31;
    int r0 = blockIdx.x * 16;
    for (int idx = tid; idx < 16 * K; idx += 256) {
        int r = idx / K, k = idx - r * K;   // K compile-time: no IDIV
        sa[k * 16 + r] = A[(size_t)(r0 + r) * K + k];
    }
    unsigned long long acc2[8];
    #pragma unroll
    for (int p = 0; p < 8; p++) acc2[p] = 0ull;
    int c = tid;

    for (int k0 = 0; k0 < K; k0 += 32) {
        #pragma unroll 8
        for (int rr = 0; rr < 32; rr++)
            fws[(w * 32 + rr) * 33 + lane] = Wt[(size_t)(w * 32 + rr) * K + k0 + lane];
        __syncthreads();
        #pragma unroll 8
        for (int kk = 0; kk < 32; kk++) {
            float wv = fws[c * 33 + kk];
            GEMM_STEP2(wv, k0 + kk)
        }
        __syncthreads();
    }

    float b = bias ? bias[c] : 0.f;
    #pragma unroll
    for (int p = 0; p < 8; p++) {
        float lo = __uint_as_float((unsigned)(acc2[p] & 0xffffffffull)) + b;
        float hi = __uint_as_float((unsigned)(acc2[p] >> 32)) + b;
        if (doRelu) { lo = fmaxf(lo, 0.f); hi = fmaxf(hi, 0.f); }
        Cout[(size_t)(r0 + 2 * p)     * HID + c] = lo;
        Cout[(size_t)(r0 + 2 * p + 1) * HID + c] = hi;
    }
}
#define GSM384 (EMB * 16 * 4 + 256 * 33 * 4)
#define GSM256 (HID * 16 * 4 + 256 * 33 * 4)

__global__ void __launch_bounds__(256) cos_update()
{
    __shared__ float q[HID];
    int tid = threadIdx.x;
    q[tid] = g_h[tid];
    __syncthreads();
    float qn = blockSum256(q[tid] * q[tid]);
    float qinv = 1.f / (sqrtf(qn) + 1e-8f);
    int w = tid >> 5, l = tid & 31;
    int j = blockIdx.x * 8 + w;
    if (j >= NS) return;
    float* s = &g_h[(size_t)(S0 + j) * HID];
    float sv[8];
    float qs = 0.f, ss = 0.f;
    #pragma unroll
    for (int e = 0; e < 8; e++) {
        float x = s[l + 32 * e];
        sv[e] = x;
        qs += q[l + 32 * e] * x;
        ss += x * x;
    }
    qs = warpSum(qs);
    ss = warpSum(ss);
    float cs = qs * qinv / (sqrtf(ss) + 1e-8f);
    #pragma unroll
    for (int e = 0; e < 8; e++)
        s[l + 32 * e] = sv[e] + 0.8f * q[l + 32 * e] * cs;
}

__global__ void __launch_bounds__(256) ln2_k(const float* __restrict__ scale,
                                             const float* __restrict__ bias)
{
    __shared__ float sc[HID], bi[HID];
    int tid = threadIdx.x, w = tid >> 5, l = tid & 31;
    sc[tid] = scale[tid];
    bi[tid] = bias[tid];
    __syncthreads();
    int row = blockIdx.x * 8 + w;
    const float* hp = &g_h[(size_t)row * HID];
    float v[8];
    float s = 0.f;
    #pragma unroll
    for (int e = 0; e < 8; e++) { v[e] = hp[l + 32 * e]; s += v[e]; }
    float mu = warpSum(s) * (1.f / HID);
    float ss = 0.f;
    #pragma unroll
    for (int e = 0; e < 8; e++) { v[e] -= mu; ss += v[e] * v[e]; }
    float rs = rsqrtf(warpSum(ss) * (1.f / HID) + 1e-5f);
    float* xp = &g_x[(size_t)row * HID];
    #pragma unroll
    for (int e = 0; e < 8; e++)
        xp[l + 32 * e] = v[e] * rs * sc[l + 32 * e] + bi[l + 32 * e];
}

__global__ void __launch_bounds__(256) srcdst_k(const float* __restrict__ ga)
{
    int w = threadIdx.x >> 5, l = threadIdx.x & 31;
    int gid = blockIdx.x * 8 + w;
    int n = gid >> 2, hh = gid & 3;
    const float* wp = &g_Wh[(size_t)n * HID + hh * HD];
    float v0 = wp[l], v1 = wp[l + 32];
    const float* a = ga + hh * 2 * HD;
    float s = v0 * a[l] + v1 * a[l + 32];
    float d = v0 * a[HD + l] + v1 * a[HD + l + 32];
    s = warpSum(s);
    d = warpSum(d);
    if (l == 0) { g_src[hh * T_N + n] = s; g_dst[hh * T_N + n] = d; }
}

__global__ void __launch_bounds__(256) dmax_k()
{
    int h = blockIdx.x;
    float m = -1e30f;
    for (int i = threadIdx.x; i < T_N; i += 256) m = fmaxf(m, g_dst[h * T_N + i]);
    __shared__ float sh[8];
    int w = threadIdx.x >> 5, l = threadIdx.x & 31;
    m = warpMax(m);
    if (l == 0) sh[w] = m;
    __syncthreads();
    if (threadIdx.x == 0) {
        float mm = sh[0];
        #pragma unroll
        for (int i = 1; i < 8; i++) mm = fmaxf(mm, sh[i]);
        g_dmax[h] = mm;
    }
}

// ============== attention, 4-deep pipeline + fused combine ==============
__global__ void __launch_bounds__(256) attn_tc(const int* __restrict__ adj)
{
    extern __shared__ char dsm[];
    uint32_t raw = s2u(dsm);
    uint32_t base = (raw + 1023u) & ~1023u;
    char* smc = dsm + (base - raw);
    float* zfin = (float*)(smc + SM_ZF);

    int tid = threadIdx.x, w = tid >> 5, lane = tid & 31;
    int h = blockIdx.x & 3;
    int i0 = (blockIdx.x >> 2) * 128;

    const float L2E = 1.44269504f;
    float srcv[16], mlog[16], zacc[16];
    float dmax = g_dmax[h];
    #pragma unroll
    for (int i = 0; i < 16; i++) {
        float s = g_src[h * T_N + i0 + w * 16 + i];
        float m = s + dmax;
        m = fmaxf(m, 0.2f * m);
        srcv[i] = s;
        mlog[i] = m * L2E;
        zacc[i] = 0.f;
    }

    const int* adjp = adj + (size_t)(i0 + w * 16) * T_N + lane;
    const float* dstp = g_dst + h * T_N + lane;
    const float* whp0 = g_Wh + h * 64;
    const int NT = T_N / 32;

    int av[16];
    float dval;
    #pragma unroll
    for (int i = 0; i < 16; i++) av[i] = adjp[(size_t)i * T_N];
    dval = dstp[0];

#if HAS_TC
    if (w == 0)
        asm volatile("tcgen05.alloc.cta_group::1.sync.aligned.shared::cta.b32 [%0], %1;"
                     :: "r"(base + SM_TPTR), "r"(64u) : "memory");
    if (tid == 0) {
        #pragma unroll
        for (int b = 0; b < 4; b++) mbar_init(base + SM_MB(b), 1);
    }
    __syncthreads();
    uint32_t tmem;
    asm volatile("ld.shared.b32 %0, [%1];" : "=r"(tmem) : "r"(base + SM_TPTR));

    // precomputed B staging: store offsets (swizzle resolved) + load pointers
    uint32_t boffq[8];
    const float* bptr[8];
    #pragma unroll
    for (int q = 0; q < 8; q++) {
        int idx = tid + q * 256;
        int n = idx & 63, k = idx >> 6;
        boffq[q] = (uint32_t)(n * 128) + (((uint32_t)(k * 4)) ^ (uint32_t)((n & 7) << 4));
        bptr[q] = whp0 + (size_t)k * HID + n;
    }
    float bv[8];
    #pragma unroll
    for (int q = 0; q < 8; q++) bv[q] = bptr[q][0];

    int wpar0 = 0, wpar1 = 0, wpar2 = 0, wpar3 = 0;

    for (int tb = 0; tb < NT; tb += 4) {
        #pragma unroll
        for (int b = 0; b < 4; b++) {
            const int t = tb + b;
            uint32_t Pb = base + SM_PB(b);
            uint32_t Bb = base + SM_BB(b);
            uint32_t mb = base + SM_MB(b);

            if (tb > 0) {
                if (b == 0)      { mbar_wait(mb, wpar0); wpar0 ^= 1; }
                else if (b == 1) { mbar_wait(mb, wpar1); wpar1 ^= 1; }
                else if (b == 2) { mbar_wait(mb, wpar2); wpar2 ^= 1; }
                else             { mbar_wait(mb, wpar3); wpar3 ^= 1; }
            }

            // stage prefetched B values
            #pragma unroll
            for (int q = 0; q < 8; q++) sts_tf32(Bb + boffq[q], bv[q]);

            // P tile (prefetched adj/dst); swizzle xor term is const per i
            #pragma unroll
            for (int i = 0; i < 16; i++) {
                float ev = srcv[i] + dval;
                ev = fmaxf(ev, 0.2f * ev);
                float wv = ex2f(fmaf(ev, L2E, -mlog[i]));
                wv = av[i] ? wv : 0.f;
                zacc[i] += wv;
                sts_tf32(Pb + (uint32_t)((w * 16 + i) * 128)
                            + ((uint32_t)(lane * 4) ^ (uint32_t)((i & 7) << 4)), wv);
            }

            // prefetch next tile's adj/dst/B
            if (t < NT - 1) {
                int j1 = (t + 1) * 32;
                #pragma unroll
                for (int i = 0; i < 16; i++) av[i] = adjp[(size_t)i * T_N + j1];
                dval = dstp[j1];
                #pragma unroll
                for (int q = 0; q < 8; q++) {
                    bptr[q] += 32 * HID;
                    bv[q] = bptr[q][0];
                }
            }

            asm volatile("fence.proxy.async.shared::cta;" ::: "memory");
            __syncthreads();

            if (w == 0 && elect_one()) {
                uint64_t ad = DESC_BASE | ((uint64_t)(Pb >> 4) & 0x3FFF);
                uint64_t bd = DESC_BASE | ((uint64_t)(Bb >> 4) & 0x3FFF);
                #pragma unroll
                for (int c = 0; c < 4; c++)
                    mma_tf32_ss(tmem, ad + c * 2, bd + c * 2, TF32_IDESC,
                                (t > 0 || c > 0) ? 1u : 0u);
                tc_commit(mb);
            }
        }
    }

    #pragma unroll
    for (int i = 0; i < 16; i++) {
        float z = warpSum(zacc[i]);
        if (lane == i) zfin[w * 16 + i] = 1.f / z;
    }
    __syncthreads();

    // last tile (NT-1 = 127) used buffer 3; its commit covers ALL prior MMAs
    mbar_wait(base + SM_MB(3), wpar3);
    asm volatile("tcgen05.fence::after_thread_sync;" ::: "memory");

    if (w < 4) {
        uint32_t dr[64];
        TC_LD_X32(dr, tmem);
        TC_LD_X32(dr + 32, tmem + 32);
        asm volatile("tcgen05.wait::ld.sync.aligned;" ::: "memory");
        int row = w * 32 + lane;
        float zi = zfin[row];
        float4* hp = (float4*)&g_h[(size_t)(i0 + row) * HID + h * 64];
        #pragma unroll
        for (int q = 0; q < 16; q++) {
            float4 old = hp[q];
            float4 o;
            o.x = 0.5f * fmaxf(__uint_as_float(dr[4 * q])     * zi, 0.f) + 0.5f * old.x;
            o.y = 0.5f * fmaxf(__uint_as_float(dr[4 * q + 1]) * zi, 0.f) + 0.5f * old.y;
            o.z = 0.5f * fmaxf(__uint_as_float(dr[4 * q + 2]) * zi, 0.f) + 0.5f * old.z;
            o.w = 0.5f * fmaxf(__uint_as_float(dr[4 * q + 3]) * zi, 0.f) + 0.5f * old.w;
            hp[q] = o;
        }
    }
    __syncthreads();
    if (w == 0) {
        asm volatile("tcgen05.relinquish_alloc_permit.cta_group::1.sync.aligned;");
        asm volatile("tcgen05.dealloc.cta_group::1.sync.aligned.b32 %0, %1;"
                     :: "r"(tmem), "r"(64u));
    }
#else
    // -------- SIMT fallback (non-sm_103a passes only) --------
    float* P = (float*)smc;     // [128][33]
    int col = tid & 63, rhalf = tid >> 6;
    float acc[32];
    #pragma unroll
    for (int r = 0; r < 32; r++) acc[r] = 0.f;
    __syncthreads();

    for (int t = 0; t < NT; t++) {
        int j0 = t * 32;
        #pragma unroll
        for (int i = 0; i < 16; i++) {
            float ev = srcv[i] + dval;
            ev = fmaxf(ev, 0.2f * ev);
            float p = ex2f(fmaf(ev, L2E, -mlog[i]));
            p = av[i] ? p : 0.f;
            zacc[i] += p;
            P[(w * 16 + i) * 33 + lane] = p;
        }
        if (t < NT - 1) {
            #pragma unroll
            for (int i = 0; i < 16; i++) av[i] = adjp[(size_t)i * T_N + j0 + 32];
            dval = dstp[j0 + 32];
        }
        __syncthreads();
        const float* whc = whp0 + (size_t)j0 * HID + col;
        #pragma unroll 4
        for (int jl = 0; jl < 32; jl++) {
            float b = whc[(size_t)jl * HID];
            const float* Pc = P + (rhalf * 32) * 33 + jl;
            #pragma unroll
            for (int r = 0; r < 32; r++) acc[r] += Pc[r * 33] * b;
        }
        __syncthreads();
    }

    #pragma unroll
    for (int i = 0; i < 16; i++) {
        float z = warpSum(zacc[i]);
        if (lane == i) zfin[w * 16 + i] = 1.f / z;
    }
    __syncthreads();
    #pragma unroll
    for (int r = 0; r < 32; r++) {
        int row = rhalf * 32 + r;
        size_t gi = (size_t)(i0 + row) * HID + h * 64 + col;
        float o = acc[r] * zfin[row];
        g_h[gi] = 0.5f * fmaxf(o, 0.f) + 0.5f * g_h[gi];
    }
#endif
}

__global__ void __launch_bounds__(256) scorecos_k()
{
    __shared__ float q[HID];
    int tid = threadIdx.x;
    q[tid] = g_h[tid];
    __syncthreads();
    float qn = blockSum256(q[tid] * q[tid]);
    float qinv = 1.f / (sqrtf(qn) + 1e-8f);
    int w = tid >> 5, l = tid & 31;
    int j = blockIdx.x * 8 + w;
    if (j >= NS) return;
    const float* s = &g_h[(size_t)(S0 + j) * HID];
    float qs = 0.f, ss = 0.f;
    #pragma unroll
    for (int e = 0; e < 8; e++) {
        float x = s[l + 32 * e];
        qs += q[l + 32 * e] * x;
        ss += x * x;
    }
    qs = warpSum(qs);
    ss = warpSum(ss);
    if (l == 0) {
        g_scores[j] = qs * (1.0f / 16.0f);
        g_cosf[j] = qs * qinv / (sqrtf(ss) + 1e-8f);
    }
}

__global__ void __launch_bounds__(1024) softmax_k()
{
    __shared__ float sh[32];
    int tid = threadIdx.x, w = tid >> 5, l = tid & 31;

    float m = -1e30f;
    for (int i = tid; i < NS; i += 1024) m = fmaxf(m, g_scores[i]);
    m = warpMax(m);
    if (l == 0) sh[w] = m;
    __syncthreads();
    if (w == 0) { float mm = sh[l]; mm = warpMax(mm); if (l == 0) sh[0] = mm; }
    __syncthreads();
    m = sh[0];
    __syncthreads();

    float sum = 0.f;
    for (int i = tid; i < NS; i += 1024) {
        float e = __expf(g_scores[i] - m);
        g_aw[i] = e;
        sum += e;
    }
    sum = warpSum(sum);
    if (l == 0) sh[w] = sum;
    __syncthreads();
    if (w == 0) { float ss = sh[l]; ss = warpSum(ss); if (l == 0) sh[0] = ss; }
    __syncthreads();
    float inv = 1.f / sh[0];
    for (int i = tid; i < NS; i += 1024) g_aw[i] *= inv;
}

__global__ void __launch_bounds__(256) fusion_k(const float* __restrict__ fw,
                                                const float* __restrict__ fb,
                                                const float* __restrict__ ow,
                                                const float* __restrict__ obp,
                                                float* __restrict__ out)
{
    __shared__ float fws[256][33];
    __shared__ __align__(16) float feat_s[32][20];
    __shared__ float awv[16], cosv[16];
    __shared__ float red2[16][8];
    int tid = threadIdx.x;
    int w = tid >> 5, lane = tid & 31;
    int j0 = blockIdx.x * 16;

    if (tid < 16) {
        int j = j0 + tid;
        awv[tid]  = (j < NS) ? g_aw[j]   : 0.f;
        cosv[tid] = (j < NS) ? g_cosf[j] : 0.f;
    }
    __syncthreads();

    unsigned long long acc2[8];
    #pragma unroll
    for (int i = 0; i < 8; i++) acc2[i] = 0ull;
    int c = tid;

    for (int k0 = 0; k0 < 512; k0 += 32) {
        #pragma unroll 8
        for (int rr = 0; rr < 32; rr++)
            fws[w * 32 + rr][lane] = fw[(size_t)(w * 32 + rr) * 514 + k0 + lane];
        #pragma unroll
        for (int q = 0; q < 2; q++) {
            int idx = tid + q * 256;
            int r = idx >> 5, kk = idx & 31;
            int k = k0 + kk;
            int j = j0 + r;
            float v = 0.f;
            if (j < NS) {
                if (k < 256) v = g_h[(size_t)(S0 + j) * HID + k];
                else         v = g_h[k - 256] * (awv[r] + 0.5f);
            }
            feat_s[kk][r] = v;
        }
        __syncthreads();

        #pragma unroll 8
        for (int kk = 0; kk < 32; kk++) {
            float wv = fws[c][kk];
            unsigned long long wvd;
            asm("mov.b64 %0, {%1,%1};" : "=l"(wvd) : "r"(__float_as_uint(wv)));
            const ulonglong2* fp = (const ulonglong2*)&feat_s[kk][0];
            #pragma unroll
            for (int q = 0; q < 4; q++) {
                ulonglong2 fv = fp[q];
                asm("fma.rn.f32x2 %0, %1, %2, %0;" : "+l"(acc2[2*q  ]) : "l"(fv.x), "l"(wvd));
                asm("fma.rn.f32x2 %0, %1, %2, %0;" : "+l"(acc2[2*q+1]) : "l"(fv.y), "l"(wvd));
            }
        }
        __syncthreads();
    }

    float acc[16];
    #pragma unroll
    for (int q = 0; q < 8; q++) {
        acc[2*q]   = __uint_as_float((unsigned)(acc2[q] & 0xffffffffull));
        acc[2*q+1] = __uint_as_float((unsigned)(acc2[q] >> 32));
    }
    float w512 = fw[(size_t)c * 514 + 512];
    float w513 = fw[(size_t)c * 514 + 513];
    #pragma unroll
    for (int r = 0; r < 16; r++) acc[r] += w512 * cosv[r] + w513 * awv[r];

    float fbv = fb[c];
    float owv = ow[c];
    #pragma unroll
    for (int r = 0; r < 16; r++) {
        float gv = fmaxf(acc[r] + fbv, 0.f) * owv;
        gv = warpSum(gv);
        if (lane == 0) red2[r][w] = gv;
    }
    __syncthreads();
    if (tid < 16) {
        float s = 0.f;
        #pragma unroll
        for (int ww = 0; ww < 8; ww++) s += red2[tid][ww];
        int j = j0 + tid;
        if (j < NS) out[j] = s + obp[0] + 0.5f * cosv[tid];
    }
}

// ---------------- launch ----------------
extern "C" void kernel_launch(void* const* d_in, const int* in_sizes, int n_in,
                              void* d_out, int out_size)
{
    const float* emb    = (const float*)d_in[0];
    const int*   adj    = (const int*)  d_in[1];
    const float* proj_w = (const float*)d_in[3];
    const float* proj_b = (const float*)d_in[4];
    const float* ln_s   = (const float*)d_in[5];
    const float* ln_b   = (const float*)d_in[6];
    const float* gat_W  = (const float*)d_in[7];
    const float* gat_a  = (const float*)d_in[8];
    const float* fw     = (const float*)d_in[9];
    const float* fb     = (const float*)d_in[10];
    const float* ow     = (const float*)d_in[11];
    const float* ob     = (const float*)d_in[12];
    float* out = (float*)d_out;

    float *hP, *xP, *whP;
    cudaGetSymbolAddress((void**)&hP,  g_h);
    cudaGetSymbolAddress((void**)&xP,  g_x);
    cudaGetSymbolAddress((void**)&whP, g_Wh);

    cudaFuncSetAttribute(attn_tc, cudaFuncAttributeMaxDynamicSharedMemorySize, SM_TOTAL);
    cudaFuncSetAttribute(gemm16t<EMB>, cudaFuncAttributeMaxDynamicSharedMemorySize, GSM384);
    cudaFuncSetAttribute(gemm16t<HID>, cudaFuncAttributeMaxDynamicSharedMemorySize, GSM256);

    gemm16t<EMB><<<T_N / 16, 256, GSM384>>>(emb, proj_w, proj_b, hP, 1);
    cos_update<<<(NS + 7) / 8, 256>>>();

    for (int L = 0; L < 2; L++) {
        ln2_k<<<T_N / 8, 256>>>(ln_s + L * HID, ln_b + L * HID);
        gemm16t<HID><<<T_N / 16, 256, GSM256>>>(xP, gat_W + (size_t)L * HID * HID, nullptr, whP, 0);
        srcdst_k<<<T_N * NH / 8, 256>>>(gat_a + L * NH * 2 * HD);
        dmax_k<<<NH, 256>>>();
        attn_tc<<<128, 256, SM_TOTAL>>>(adj);
    }

    scorecos_k<<<(NS + 7) / 8, 256>>>();
    softmax_k<<<1, 1024>>>();
    fusion_k<<<(NS + 15) / 16, 256>>>(fw, fb, ow, ob, out);
}

// round 10
// speedup vs baseline: 2.2984x; 1.1668x over previous
#include <cuda_runtime.h>
#include <math.h>
#include <cstdint>

#define T_N  4096
#define EMB  384
#define HID  256
#define NH   4
#define HD   64
#define MD   32
#define S0   33
#define NS   4063

#if defined(__CUDA_ARCH_FEAT_SM103_ALL) || defined(__CUDA_ARCH_FEAT_SM100_ALL) || defined(__CUDA_ARCH_FEAT_SM101_ALL)
#define HAS_TC 1
#else
#define HAS_TC 0
#endif

__device__ float g_h  [T_N * HID];
__device__ float g_x  [T_N * HID];
__device__ float g_Wh [T_N * HID];
__device__ float g_src[NH * T_N];
__device__ float g_dst[NH * T_N];
__device__ float g_dmax[NH];
__device__ float g_scores[NS];
__device__ float g_cosf[NS];
__device__ float g_aw[NS];

__device__ __forceinline__ float warpSum(float v) {
    #pragma unroll
    for (int o = 16; o; o >>= 1) v += __shfl_xor_sync(0xffffffffu, v, o);
    return v;
}
__device__ __forceinline__ float warpMax(float v) {
    #pragma unroll
    for (int o = 16; o; o >>= 1) v = fmaxf(v, __shfl_xor_sync(0xffffffffu, v, o));
    return v;
}
__device__ float blockSum256(float v) {
    __shared__ float sh[8];
    int w = threadIdx.x >> 5, l = threadIdx.x & 31;
    v = warpSum(v);
    if (l == 0) sh[w] = v;
    __syncthreads();
    float s = (threadIdx.x < 8) ? sh[threadIdx.x] : 0.f;
    if (w == 0) { s = warpSum(s); if (l == 0) sh[0] = s; }
    __syncthreads();
    float r = sh[0];
    __syncthreads();
    return r;
}

__device__ __forceinline__ uint32_t s2u(const void* p) {
    uint32_t a;
    asm("{ .reg .u64 t; cvta.to.shared.u64 t, %1; cvt.u32.u64 %0, t; }"
        : "=r"(a) : "l"(p));
    return a;
}
__device__ __forceinline__ float ex2f(float x) {
    float r;
    asm("ex2.approx.f32 %0, %1;" : "=f"(r) : "f"(x));
    return r;
}

#if HAS_TC
__device__ __forceinline__ uint32_t elect_one() {
    uint32_t pred;
    asm volatile("{\n\t.reg .pred p;\n\telect.sync _|p, 0xFFFFFFFF;\n\t"
                 "selp.b32 %0, 1, 0, p;\n\t}" : "=r"(pred));
    return pred;
}
__device__ __forceinline__ void mbar_init(uint32_t addr, uint32_t cnt) {
    asm volatile("mbarrier.init.shared.b64 [%0], %1;" :: "r"(addr), "r"(cnt) : "memory");
}
__device__ __forceinline__ void mbar_wait(uint32_t addr, uint32_t parity) {
    asm volatile(
        "{\n\t.reg .pred P;\n\t"
        "WL%=:\n\t"
        "mbarrier.try_wait.parity.acquire.cta.shared::cta.b64 P, [%0], %1, 0x989680;\n\t"
        "@P bra WD%=;\n\t"
        "bra WL%=;\n\t"
        "WD%=:\n\t}"
        :: "r"(addr), "r"(parity) : "memory");
}
__device__ __forceinline__ void sts_tf32(uint32_t addr, float v) {
    uint32_t t;
    asm("cvt.rn.tf32.f32 %0, %1;" : "=r"(t) : "f"(v));
    asm volatile("st.shared.b32 [%0], %1;" :: "r"(addr), "r"(t) : "memory");
}
__device__ __forceinline__ void mma_tf32_ss(uint32_t d_tmem, uint64_t a_desc,
                                            uint64_t b_desc, uint32_t idesc,
                                            uint32_t en) {
    asm volatile(
        "{\n\t.reg .pred p;\n\tsetp.ne.u32 p, %4, 0;\n\t"
        "tcgen05.mma.cta_group::1.kind::tf32 [%0], %1, %2, %3, {%5, %5, %5, %5}, p;\n\t}"
        :: "r"(d_tmem), "l"(a_desc), "l"(b_desc), "r"(idesc), "r"(en), "r"(0u)
        : "memory");
}
__device__ __forceinline__ void tc_commit(uint32_t mbar) {
    asm volatile(
        "tcgen05.commit.cta_group::1.mbarrier::arrive::one.shared::cluster.b64 [%0];"
        :: "r"(mbar) : "memory");
}
#define TC_LD_X32(r, tmem_addr) \
    asm volatile( \
        "tcgen05.ld.sync.aligned.32x32b.x32.b32 " \
        "{%0, %1, %2, %3, %4, %5, %6, %7, " \
        " %8, %9, %10, %11, %12, %13, %14, %15, " \
        " %16, %17, %18, %19, %20, %21, %22, %23, " \
        " %24, %25, %26, %27, %28, %29, %30, %31}, [%32];" \
        : "=r"((r)[0]),  "=r"((r)[1]),  "=r"((r)[2]),  "=r"((r)[3]), \
          "=r"((r)[4]),  "=r"((r)[5]),  "=r"((r)[6]),  "=r"((r)[7]), \
          "=r"((r)[8]),  "=r"((r)[9]),  "=r"((r)[10]), "=r"((r)[11]), \
          "=r"((r)[12]), "=r"((r)[13]), "=r"((r)[14]), "=r"((r)[15]), \
          "=r"((r)[16]), "=r"((r)[17]), "=r"((r)[18]), "=r"((r)[19]), \
          "=r"((r)[20]), "=r"((r)[21]), "=r"((r)[22]), "=r"((r)[23]), \
          "=r"((r)[24]), "=r"((r)[25]), "=r"((r)[26]), "=r"((r)[27]), \
          "=r"((r)[28]), "=r"((r)[29]), "=r"((r)[30]), "=r"((r)[31]) \
        : "r"(tmem_addr))
#endif // HAS_TC

// smem desc: SW128, version=1, SBO=64, LBO=1
#define DESC_BASE ((2ull << 61) | (1ull << 46) | (64ull << 32) | (1ull << 16))
// idesc: dtype=F32, atype=TF32, btype=TF32, N=64, M=128
#define TF32_IDESC ((1u << 4) | (2u << 7) | (2u << 10) | (8u << 17) | (8u << 24))

// attn smem: 4-deep ring
#define SM_PB(b) ((b) * 16384)
#define SM_BB(b) (65536 + (b) * 8192)
#define SM_TPTR  98304
#define SM_MB(b) (98320 + (b) * 8)
#define SM_ZF    98368
#define SM_TOTAL (98880 + 1024)

// gemm_tc smem: double-buffered A (128x32) + B (64x32)
#define GM_AB(b)  ((b) * 16384)
#define GM_BB(b)  (32768 + (b) * 8192)
#define GM_TPTR   49152
#define GM_MB(b)  (49168 + (b) * 8)
#define GM_BIAS   49184
#define GM_TOTAL  (49184 + 256 + 1024)

// ============== tcgen05 tf32 GEMM: C[r0:+128, c0:+64] = A[128,K] @ Wt[64,K]^T ==============
// grid = (M/128) * 4 colblocks. Same tile machinery as attn_tc.
template<int K>
__global__ void __launch_bounds__(256) gemm_tc(const float* __restrict__ A,
                                               const float* __restrict__ Wt,
                                               const float* __restrict__ bias,
                                               float* __restrict__ C,
                                               int doRelu)
{
    extern __shared__ char dsm[];
    uint32_t raw = s2u(dsm);
    uint32_t base = (raw + 1023u) & ~1023u;
    char* smc = dsm + (base - raw);

    int tid = threadIdx.x, w = tid >> 5, lane = tid & 31;
    int cb = blockIdx.x & 3;
    int r0 = (blockIdx.x >> 2) * 128;
    int c0 = cb * 64;
    const int NC = K / 32;

#if HAS_TC
    if (w == 0)
        asm volatile("tcgen05.alloc.cta_group::1.sync.aligned.shared::cta.b32 [%0], %1;"
                     :: "r"(base + GM_TPTR), "r"(64u) : "memory");
    if (tid == 0) { mbar_init(base + GM_MB(0), 1); mbar_init(base + GM_MB(1), 1); }
    if (tid < 64) ((float*)(smc + GM_BIAS))[tid] = bias ? bias[c0 + tid] : 0.f;
    __syncthreads();
    uint32_t tmem;
    asm volatile("ld.shared.b32 %0, [%1];" : "=r"(tmem) : "r"(base + GM_TPTR));

    // A staging: 16 elems/thread; m = idx>>5 (row), k = idx&31
    uint32_t aoff[16];
    const float* aptr[16];
    float avv[16];
    #pragma unroll
    for (int q = 0; q < 16; q++) {
        int idx = tid + q * 256;
        int m = idx >> 5, k = idx & 31;
        aoff[q] = (uint32_t)(m * 128) + (((uint32_t)(k * 4)) ^ (uint32_t)((m & 7) << 4));
        aptr[q] = A + (size_t)(r0 + m) * K + k;
        avv[q] = aptr[q][0];
    }
    // B staging: 8 elems/thread; n = idx>>5, k = idx&31
    uint32_t boff[8];
    const float* bptr[8];
    float bvv[8];
    #pragma unroll
    for (int q = 0; q < 8; q++) {
        int idx = tid + q * 256;
        int n = idx >> 5, k = idx & 31;
        boff[q] = (uint32_t)(n * 128) + (((uint32_t)(k * 4)) ^ (uint32_t)((n & 7) << 4));
        bptr[q] = Wt + (size_t)(c0 + n) * K + k;
        bvv[q] = bptr[q][0];
    }

    int wp0 = 0, wp1 = 0;
    for (int t = 0; t < NC; t++) {
        int buf = t & 1;
        uint32_t Ab = base + GM_AB(buf);
        uint32_t Bb = base + GM_BB(buf);
        uint32_t mb = base + GM_MB(buf);

        if (t >= 2) {
            if (buf == 0) { mbar_wait(base + GM_MB(0), wp0); wp0 ^= 1; }
            else          { mbar_wait(base + GM_MB(1), wp1); wp1 ^= 1; }
        }

        #pragma unroll
        for (int q = 0; q < 16; q++) sts_tf32(Ab + aoff[q], avv[q]);
        #pragma unroll
        for (int q = 0; q < 8; q++)  sts_tf32(Bb + boff[q], bvv[q]);

        if (t < NC - 1) {
            #pragma unroll
            for (int q = 0; q < 16; q++) { aptr[q] += 32; avv[q] = aptr[q][0]; }
            #pragma unroll
            for (int q = 0; q < 8; q++)  { bptr[q] += 32; bvv[q] = bptr[q][0]; }
        }

        asm volatile("fence.proxy.async.shared::cta;" ::: "memory");
        __syncthreads();

        if (w == 0 && elect_one()) {
            uint64_t ad = DESC_BASE | ((uint64_t)(Ab >> 4) & 0x3FFF);
            uint64_t bd = DESC_BASE | ((uint64_t)(Bb >> 4) & 0x3FFF);
            #pragma unroll
            for (int c = 0; c < 4; c++)
                mma_tf32_ss(tmem, ad + c * 2, bd + c * 2, TF32_IDESC,
                            (t > 0 || c > 0) ? 1u : 0u);
            tc_commit(mb);
        }
    }

    // last chunk (NC-1, NC even -> buffer 1) commit covers all MMAs
    mbar_wait(base + GM_MB(1), wp1);
    asm volatile("tcgen05.fence::after_thread_sync;" ::: "memory");

    if (w < 4) {
        uint32_t dr[64];
        TC_LD_X32(dr, tmem);
        TC_LD_X32(dr + 32, tmem + 32);
        asm volatile("tcgen05.wait::ld.sync.aligned;" ::: "memory");
        int row = w * 32 + lane;
        const float* sb = (const float*)(smc + GM_BIAS);
        float4* op = (float4*)&C[(size_t)(r0 + row) * HID + c0];
        #pragma unroll
        for (int q = 0; q < 16; q++) {
            float4 o;
            o.x = __uint_as_float(dr[4 * q])     + sb[4 * q];
            o.y = __uint_as_float(dr[4 * q + 1]) + sb[4 * q + 1];
            o.z = __uint_as_float(dr[4 * q + 2]) + sb[4 * q + 2];
            o.w = __uint_as_float(dr[4 * q + 3]) + sb[4 * q + 3];
            if (doRelu) {
                o.x = fmaxf(o.x, 0.f); o.y = fmaxf(o.y, 0.f);
                o.z = fmaxf(o.z, 0.f); o.w = fmaxf(o.w, 0.f);
            }
            op[q] = o;
        }
    }
    __syncthreads();
    if (w == 0) {
        asm volatile("tcgen05.relinquish_alloc_permit.cta_group::1.sync.aligned;");
        asm volatile("tcgen05.dealloc.cta_group::1.sync.aligned.b32 %0, %1;"
                     :: "r"(tmem), "r"(64u));
    }
#else
    // SIMT fallback (non-sm_103a passes only; never runs on GB300)
    int c = tid & 63, rh = tid >> 6;
    for (int m = rh * 32; m < rh * 32 + 32; m++) {
        float acc = 0.f;
        const float* ap = A + (size_t)(r0 + m) * K;
        const float* wp2 = Wt + (size_t)(c0 + c) * K;
        for (int k = 0; k < K; k++) acc += ap[k] * wp2[k];
        float b = bias ? bias[c0 + c] : 0.f;
        float v = acc + b;
        if (doRelu) v = fmaxf(v, 0.f);
        C[(size_t)(r0 + m) * HID + c0 + c] = v;
    }
#endif
}

__global__ void __launch_bounds__(256) cos_update()
{
    __shared__ float q[HID];
    int tid = threadIdx.x;
    q[tid] = g_h[tid];
    __syncthreads();
    float qn = blockSum256(q[tid] * q[tid]);
    float qinv = 1.f / (sqrtf(qn) + 1e-8f);
    int w = tid >> 5, l = tid & 31;
    int j = blockIdx.x * 8 + w;
    if (j >= NS) return;
    float* s = &g_h[(size_t)(S0 + j) * HID];
    float sv[8];
    float qs = 0.f, ss = 0.f;
    #pragma unroll
    for (int e = 0; e < 8; e++) {
        float x = s[l + 32 * e];
        sv[e] = x;
        qs += q[l + 32 * e] * x;
        ss += x * x;
    }
    qs = warpSum(qs);
    ss = warpSum(ss);
    float cs = qs * qinv / (sqrtf(ss) + 1e-8f);
    #pragma unroll
    for (int e = 0; e < 8; e++)
        s[l + 32 * e] = sv[e] + 0.8f * q[l + 32 * e] * cs;
}

__global__ void __launch_bounds__(256) ln2_k(const float* __restrict__ scale,
                                             const float* __restrict__ bias)
{
    __shared__ float sc[HID], bi[HID];
    int tid = threadIdx.x, w = tid >> 5, l = tid & 31;
    sc[tid] = scale[tid];
    bi[tid] = bias[tid];
    __syncthreads();
    int row = blockIdx.x * 8 + w;
    const float* hp = &g_h[(size_t)row * HID];
    float v[8];
    float s = 0.f;
    #pragma unroll
    for (int e = 0; e < 8; e++) { v[e] = hp[l + 32 * e]; s += v[e]; }
    float mu = warpSum(s) * (1.f / HID);
    float ss = 0.f;
    #pragma unroll
    for (int e = 0; e < 8; e++) { v[e] -= mu; ss += v[e] * v[e]; }
    float rs = rsqrtf(warpSum(ss) * (1.f / HID) + 1e-5f);
    float* xp = &g_x[(size_t)row * HID];
    #pragma unroll
    for (int e = 0; e < 8; e++)
        xp[l + 32 * e] = v[e] * rs * sc[l + 32 * e] + bi[l + 32 * e];
}

__global__ void __launch_bounds__(256) srcdst_k(const float* __restrict__ ga)
{
    int w = threadIdx.x >> 5, l = threadIdx.x & 31;
    int gid = blockIdx.x * 8 + w;
    int n = gid >> 2, hh = gid & 3;
    const float* wp = &g_Wh[(size_t)n * HID + hh * HD];
    float v0 = wp[l], v1 = wp[l + 32];
    const float* a = ga + hh * 2 * HD;
    float s = v0 * a[l] + v1 * a[l + 32];
    float d = v0 * a[HD + l] + v1 * a[HD + l + 32];
    s = warpSum(s);
    d = warpSum(d);
    if (l == 0) { g_src[hh * T_N + n] = s; g_dst[hh * T_N + n] = d; }
}

__global__ void __launch_bounds__(256) dmax_k()
{
    int h = blockIdx.x;
    float m = -1e30f;
    for (int i = threadIdx.x; i < T_N; i += 256) m = fmaxf(m, g_dst[h * T_N + i]);
    __shared__ float sh[8];
    int w = threadIdx.x >> 5, l = threadIdx.x & 31;
    m = warpMax(m);
    if (l == 0) sh[w] = m;
    __syncthreads();
    if (threadIdx.x == 0) {
        float mm = sh[0];
        #pragma unroll
        for (int i = 1; i < 8; i++) mm = fmaxf(mm, sh[i]);
        g_dmax[h] = mm;
    }
}

// ============== attention, 4-deep pipeline + fused combine (R9, unchanged) ==============
__global__ void __launch_bounds__(256) attn_tc(const int* __restrict__ adj)
{
    extern __shared__ char dsm[];
    uint32_t raw = s2u(dsm);
    uint32_t base = (raw + 1023u) & ~1023u;
    char* smc = dsm + (base - raw);
    float* zfin = (float*)(smc + SM_ZF);

    int tid = threadIdx.x, w = tid >> 5, lane = tid & 31;
    int h = blockIdx.x & 3;
    int i0 = (blockIdx.x >> 2) * 128;

    const float L2E = 1.44269504f;
    float srcv[16], mlog[16], zacc[16];
    float dmax = g_dmax[h];
    #pragma unroll
    for (int i = 0; i < 16; i++) {
        float s = g_src[h * T_N + i0 + w * 16 + i];
        float m = s + dmax;
        m = fmaxf(m, 0.2f * m);
        srcv[i] = s;
        mlog[i] = m * L2E;
        zacc[i] = 0.f;
    }

    const int* adjp = adj + (size_t)(i0 + w * 16) * T_N + lane;
    const float* dstp = g_dst + h * T_N + lane;
    const float* whp0 = g_Wh + h * 64;
    const int NT = T_N / 32;

    int av[16];
    float dval;
    #pragma unroll
    for (int i = 0; i < 16; i++) av[i] = adjp[(size_t)i * T_N];
    dval = dstp[0];

#if HAS_TC
    if (w == 0)
        asm volatile("tcgen05.alloc.cta_group::1.sync.aligned.shared::cta.b32 [%0], %1;"
                     :: "r"(base + SM_TPTR), "r"(64u) : "memory");
    if (tid == 0) {
        #pragma unroll
        for (int b = 0; b < 4; b++) mbar_init(base + SM_MB(b), 1);
    }
    __syncthreads();
    uint32_t tmem;
    asm volatile("ld.shared.b32 %0, [%1];" : "=r"(tmem) : "r"(base + SM_TPTR));

    uint32_t boffq[8];
    const float* bptr[8];
    #pragma unroll
    for (int q = 0; q < 8; q++) {
        int idx = tid + q * 256;
        int n = idx & 63, k = idx >> 6;
        boffq[q] = (uint32_t)(n * 128) + (((uint32_t)(k * 4)) ^ (uint32_t)((n & 7) << 4));
        bptr[q] = whp0 + (size_t)k * HID + n;
    }
    float bv[8];
    #pragma unroll
    for (int q = 0; q < 8; q++) bv[q] = bptr[q][0];

    int wpar0 = 0, wpar1 = 0, wpar2 = 0, wpar3 = 0;

    for (int tb = 0; tb < NT; tb += 4) {
        #pragma unroll
        for (int b = 0; b < 4; b++) {
            const int t = tb + b;
            uint32_t Pb = base + SM_PB(b);
            uint32_t Bb = base + SM_BB(b);
            uint32_t mb = base + SM_MB(b);

            if (tb > 0) {
                if (b == 0)      { mbar_wait(mb, wpar0); wpar0 ^= 1; }
                else if (b == 1) { mbar_wait(mb, wpar1); wpar1 ^= 1; }
                else if (b == 2) { mbar_wait(mb, wpar2); wpar2 ^= 1; }
                else             { mbar_wait(mb, wpar3); wpar3 ^= 1; }
            }

            #pragma unroll
            for (int q = 0; q < 8; q++) sts_tf32(Bb + boffq[q], bv[q]);

            #pragma unroll
            for (int i = 0; i < 16; i++) {
                float ev = srcv[i] + dval;
                ev = fmaxf(ev, 0.2f * ev);
                float wv = ex2f(fmaf(ev, L2E, -mlog[i]));
                wv = av[i] ? wv : 0.f;
                zacc[i] += wv;
                sts_tf32(Pb + (uint32_t)((w * 16 + i) * 128)
                            + ((uint32_t)(lane * 4) ^ (uint32_t)((i & 7) << 4)), wv);
            }

            if (t < NT - 1) {
                int j1 = (t + 1) * 32;
                #pragma unroll
                for (int i = 0; i < 16; i++) av[i] = adjp[(size_t)i * T_N + j1];
                dval = dstp[j1];
                #pragma unroll
                for (int q = 0; q < 8; q++) {
                    bptr[q] += 32 * HID;
                    bv[q] = bptr[q][0];
                }
            }

            asm volatile("fence.proxy.async.shared::cta;" ::: "memory");
            __syncthreads();

            if (w == 0 && elect_one()) {
                uint64_t ad = DESC_BASE | ((uint64_t)(Pb >> 4) & 0x3FFF);
                uint64_t bd = DESC_BASE | ((uint64_t)(Bb >> 4) & 0x3FFF);
                #pragma unroll
                for (int c = 0; c < 4; c++)
                    mma_tf32_ss(tmem, ad + c * 2, bd + c * 2, TF32_IDESC,
                                (t > 0 || c > 0) ? 1u : 0u);
                tc_commit(mb);
            }
        }
    }

    #pragma unroll
    for (int i = 0; i < 16; i++) {
        float z = warpSum(zacc[i]);
        if (lane == i) zfin[w * 16 + i] = 1.f / z;
    }
    __syncthreads();

    mbar_wait(base + SM_MB(3), wpar3);
    asm volatile("tcgen05.fence::after_thread_sync;" ::: "memory");

    if (w < 4) {
        uint32_t dr[64];
        TC_LD_X32(dr, tmem);
        TC_LD_X32(dr + 32, tmem + 32);
        asm volatile("tcgen05.wait::ld.sync.aligned;" ::: "memory");
        int row = w * 32 + lane;
        float zi = zfin[row];
        float4* hp = (float4*)&g_h[(size_t)(i0 + row) * HID + h * 64];
        #pragma unroll
        for (int q = 0; q < 16; q++) {
            float4 old = hp[q];
            float4 o;
            o.x = 0.5f * fmaxf(__uint_as_float(dr[4 * q])     * zi, 0.f) + 0.5f * old.x;
            o.y = 0.5f * fmaxf(__uint_as_float(dr[4 * q + 1]) * zi, 0.f) + 0.5f * old.y;
            o.z = 0.5f * fmaxf(__uint_as_float(dr[4 * q + 2]) * zi, 0.f) + 0.5f * old.z;
            o.w = 0.5f * fmaxf(__uint_as_float(dr[4 * q + 3]) * zi, 0.f) + 0.5f * old.w;
            hp[q] = o;
        }
    }
    __syncthreads();
    if (w == 0) {
        asm volatile("tcgen05.relinquish_alloc_permit.cta_group::1.sync.aligned;");
        asm volatile("tcgen05.dealloc.cta_group::1.sync.aligned.b32 %0, %1;"
                     :: "r"(tmem), "r"(64u));
    }
#else
    float* P = (float*)smc;
    int col = tid & 63, rhalf = tid >> 6;
    float acc[32];
    #pragma unroll
    for (int r = 0; r < 32; r++) acc[r] = 0.f;
    __syncthreads();

    for (int t = 0; t < NT; t++) {
        int j0 = t * 32;
        #pragma unroll
        for (int i = 0; i < 16; i++) {
            float ev = srcv[i] + dval;
            ev = fmaxf(ev, 0.2f * ev);
            float p = ex2f(fmaf(ev, L2E, -mlog[i]));
            p = av[i] ? p : 0.f;
            zacc[i] += p;
            P[(w * 16 + i) * 33 + lane] = p;
        }
        if (t < NT - 1) {
            #pragma unroll
            for (int i = 0; i < 16; i++) av[i] = adjp[(size_t)i * T_N + j0 + 32];
            dval = dstp[j0 + 32];
        }
        __syncthreads();
        const float* whc = whp0 + (size_t)j0 * HID + col;
        #pragma unroll 4
        for (int jl = 0; jl < 32; jl++) {
            float b = whc[(size_t)jl * HID];
            const float* Pc = P + (rhalf * 32) * 33 + jl;
            #pragma unroll
            for (int r = 0; r < 32; r++) acc[r] += Pc[r * 33] * b;
        }
        __syncthreads();
    }

    #pragma unroll
    for (int i = 0; i < 16; i++) {
        float z = warpSum(zacc[i]);
        if (lane == i) zfin[w * 16 + i] = 1.f / z;
    }
    __syncthreads();
    #pragma unroll
    for (int r = 0; r < 32; r++) {
        int row = rhalf * 32 + r;
        size_t gi = (size_t)(i0 + row) * HID + h * 64 + col;
        float o = acc[r] * zfin[row];
        g_h[gi] = 0.5f * fmaxf(o, 0.f) + 0.5f * g_h[gi];
    }
#endif
}

__global__ void __launch_bounds__(256) scorecos_k()
{
    __shared__ float q[HID];
    int tid = threadIdx.x;
    q[tid] = g_h[tid];
    __syncthreads();
    float qn = blockSum256(q[tid] * q[tid]);
    float qinv = 1.f / (sqrtf(qn) + 1e-8f);
    int w = tid >> 5, l = tid & 31;
    int j = blockIdx.x * 8 + w;
    if (j >= NS) return;
    const float* s = &g_h[(size_t)(S0 + j) * HID];
    float qs = 0.f, ss = 0.f;
    #pragma unroll
    for (int e = 0; e < 8; e++) {
        float x = s[l + 32 * e];
        qs += q[l + 32 * e] * x;
        ss += x * x;
    }
    qs = warpSum(qs);
    ss = warpSum(ss);
    if (l == 0) {
        g_scores[j] = qs * (1.0f / 16.0f);
        g_cosf[j] = qs * qinv / (sqrtf(ss) + 1e-8f);
    }
}

__global__ void __launch_bounds__(1024) softmax_k()
{
    __shared__ float sh[32];
    int tid = threadIdx.x, w = tid >> 5, l = tid & 31;

    float m = -1e30f;
    for (int i = tid; i < NS; i += 1024) m = fmaxf(m, g_scores[i]);
    m = warpMax(m);
    if (l == 0) sh[w] = m;
    __syncthreads();
    if (w == 0) { float mm = sh[l]; mm = warpMax(mm); if (l == 0) sh[0] = mm; }
    __syncthreads();
    m = sh[0];
    __syncthreads();

    float sum = 0.f;
    for (int i = tid; i < NS; i += 1024) {
        float e = __expf(g_scores[i] - m);
        g_aw[i] = e;
        sum += e;
    }
    sum = warpSum(sum);
    if (l == 0) sh[w] = sum;
    __syncthreads();
    if (w == 0) { float ss = sh[l]; ss = warpSum(ss); if (l == 0) sh[0] = ss; }
    __syncthreads();
    float inv = 1.f / sh[0];
    for (int i = tid; i < NS; i += 1024) g_aw[i] *= inv;
}

__global__ void __launch_bounds__(256) fusion_k(const float* __restrict__ fw,
                                                const float* __restrict__ fb,
                                                const float* __restrict__ ow,
                                                const float* __restrict__ obp,
                                                float* __restrict__ out)
{
    __shared__ float fws[256][33];
    __shared__ __align__(16) float feat_s[32][20];
    __shared__ float awv[16], cosv[16];
    __shared__ float red2[16][8];
    int tid = threadIdx.x;
    int w = tid >> 5, lane = tid & 31;
    int j0 = blockIdx.x * 16;

    if (tid < 16) {
        int j = j0 + tid;
        awv[tid]  = (j < NS) ? g_aw[j]   : 0.f;
        cosv[tid] = (j < NS) ? g_cosf[j] : 0.f;
    }
    __syncthreads();

    unsigned long long acc2[8];
    #pragma unroll
    for (int i = 0; i < 8; i++) acc2[i] = 0ull;
    int c = tid;

    for (int k0 = 0; k0 < 512; k0 += 32) {
        #pragma unroll 8
        for (int rr = 0; rr < 32; rr++)
            fws[w * 32 + rr][lane] = fw[(size_t)(w * 32 + rr) * 514 + k0 + lane];
        #pragma unroll
        for (int q = 0; q < 2; q++) {
            int idx = tid + q * 256;
            int r = idx >> 5, kk = idx & 31;
            int k = k0 + kk;
            int j = j0 + r;
            float v = 0.f;
            if (j < NS) {
                if (k < 256) v = g_h[(size_t)(S0 + j) * HID + k];
                else         v = g_h[k - 256] * (awv[r] + 0.5f);
            }
            feat_s[kk][r] = v;
        }
        __syncthreads();

        #pragma unroll 8
        for (int kk = 0; kk < 32; kk++) {
            float wv = fws[c][kk];
            unsigned long long wvd;
            asm("mov.b64 %0, {%1,%1};" : "=l"(wvd) : "r"(__float_as_uint(wv)));
            const ulonglong2* fp = (const ulonglong2*)&feat_s[kk][0];
            #pragma unroll
            for (int q = 0; q < 4; q++) {
                ulonglong2 fv = fp[q];
                asm("fma.rn.f32x2 %0, %1, %2, %0;" : "+l"(acc2[2*q  ]) : "l"(fv.x), "l"(wvd));
                asm("fma.rn.f32x2 %0, %1, %2, %0;" : "+l"(acc2[2*q+1]) : "l"(fv.y), "l"(wvd));
            }
        }
        __syncthreads();
    }

    float acc[16];
    #pragma unroll
    for (int q = 0; q < 8; q++) {
        acc[2*q]   = __uint_as_float((unsigned)(acc2[q] & 0xffffffffull));
        acc[2*q+1] = __uint_as_float((unsigned)(acc2[q] >> 32));
    }
    float w512 = fw[(size_t)c * 514 + 512];
    float w513 = fw[(size_t)c * 514 + 513];
    #pragma unroll
    for (int r = 0; r < 16; r++) acc[r] += w512 * cosv[r] + w513 * awv[r];

    float fbv = fb[c];
    float owv = ow[c];
    #pragma unroll
    for (int r = 0; r < 16; r++) {
        float gv = fmaxf(acc[r] + fbv, 0.f) * owv;
        gv = warpSum(gv);
        if (lane == 0) red2[r][w] = gv;
    }
    __syncthreads();
    if (tid < 16) {
        float s = 0.f;
        #pragma unroll
        for (int ww = 0; ww < 8; ww++) s += red2[tid][ww];
        int j = j0 + tid;
        if (j < NS) out[j] = s + obp[0] + 0.5f * cosv[tid];
    }
}

// ---------------- launch ----------------
extern "C" void kernel_launch(void* const* d_in, const int* in_sizes, int n_in,
                              void* d_out, int out_size)
{
    const float* emb    = (const float*)d_in[0];
    const int*   adj    = (const int*)  d_in[1];
    const float* proj_w = (const float*)d_in[3];
    const float* proj_b = (const float*)d_in[4];
    const float* ln_s   = (const float*)d_in[5];
    const float* ln_b   = (const float*)d_in[6];
    const float* gat_W  = (const float*)d_in[7];
    const float* gat_a  = (const float*)d_in[8];
    const float* fw     = (const float*)d_in[9];
    const float* fb     = (const float*)d_in[10];
    const float* ow     = (const float*)d_in[11];
    const float* ob     = (const float*)d_in[12];
    float* out = (float*)d_out;

    float *hP, *xP, *whP;
    cudaGetSymbolAddress((void**)&hP,  g_h);
    cudaGetSymbolAddress((void**)&xP,  g_x);
    cudaGetSymbolAddress((void**)&whP, g_Wh);

    cudaFuncSetAttribute(attn_tc, cudaFuncAttributeMaxDynamicSharedMemorySize, SM_TOTAL);
    cudaFuncSetAttribute(gemm_tc<EMB>, cudaFuncAttributeMaxDynamicSharedMemorySize, GM_TOTAL);
    cudaFuncSetAttribute(gemm_tc<HID>, cudaFuncAttributeMaxDynamicSharedMemorySize, GM_TOTAL);

    gemm_tc<EMB><<<(T_N / 128) * 4, 256, GM_TOTAL>>>(emb, proj_w, proj_b, hP, 1);
    cos_update<<<(NS + 7) / 8, 256>>>();

    for (int L = 0; L < 2; L++) {
        ln2_k<<<T_N / 8, 256>>>(ln_s + L * HID, ln_b + L * HID);
        gemm_tc<HID><<<(T_N / 128) * 4, 256, GM_TOTAL>>>(xP, gat_W + (size_t)L * HID * HID, nullptr, whP, 0);
        srcdst_k<<<T_N * NH / 8, 256>>>(gat_a + L * NH * 2 * HD);
        dmax_k<<<NH, 256>>>();
        attn_tc<<<128, 256, SM_TOTAL>>>(adj);
    }

    scorecos_k<<<(NS + 7) / 8, 256>>>();
    softmax_k<<<1, 1024>>>();
    fusion_k<<<(NS + 15) / 16, 256>>>(fw, fb, ow, ob, out);
}